// round 7
// baseline (speedup 1.0000x reference)
#include <cuda_runtime.h>
#include <math.h>

#define BB 8
#define NN 1024
#define EE 16384
#define FF 96
#define FE 32
#define HH 12
#define DD 8
#define KM 224           // 2F + Fe
#define KMP 228          // padded stride: conflict-free LDS.128
#define K2 192           // 2F
#define K2P 196
#define EPB 8            // rows/edges per warp per iteration
#define LN_EPS 1e-3f
#define ATT_SCALE 0.35355339059327373f

typedef unsigned long long u64;

// ---------------- packed f32x2 helpers ----------------
__device__ __forceinline__ u64 ffma2(u64 a, u64 b, u64 c){
    u64 d; asm("fma.rn.f32x2 %0, %1, %2, %3;" : "=l"(d) : "l"(a), "l"(b), "l"(c)); return d;
}
__device__ __forceinline__ u64 fmul2(u64 a, u64 b){
    u64 d; asm("mul.rn.f32x2 %0, %1, %2;" : "=l"(d) : "l"(a), "l"(b)); return d;
}
__device__ __forceinline__ u64 pack2(float a, float b){
    u64 r; asm("mov.b64 %0, {%1, %2};" : "=l"(r) : "f"(a), "f"(b)); return r;
}
__device__ __forceinline__ float2 unpack2(u64 v){
    float2 f; asm("mov.b64 {%0, %1}, %2;" : "=f"(f.x), "=f"(f.y) : "l"(v)); return f;
}
__device__ __forceinline__ float psum2(u64 v){ float2 f = unpack2(v); return f.x + f.y; }

__device__ __forceinline__ float gelu_erf(float x){
    return 0.5f * x * (1.0f + erff(x * 0.70710678118654752f));
}

// ---------------- scratch ----------------
__device__ float g_agg [BB*NN*FF];
__device__ float g_q   [BB*HH*NN*DD];
__device__ float g_k   [BB*HH*NN*DD];
__device__ float g_v   [BB*HH*NN*DD];
__device__ float g_gate[BB*HH*NN*DD];
__device__ float g_att [BB*NN*FF];

// ---------------- helpers ----------------
__global__ void zero_agg_kernel(){
    int i = blockIdx.x*blockDim.x + threadIdx.x;
    if (i < BB*NN*FF) g_agg[i] = 0.0f;
}

__global__ void passthrough_kernel(const int* __restrict__ edges,
                                   const float* __restrict__ ew,
                                   const float* __restrict__ ed,
                                   float* __restrict__ out_edges,
                                   float* __restrict__ out_ew,
                                   float* __restrict__ out_ed){
    int i = blockIdx.x*blockDim.x + threadIdx.x;
    if (i < BB*EE*2){ out_edges[i] = (float)edges[i]; out_ed[i] = ed[i]; }
    if (i < BB*EE)  out_ew[i] = ew[i];
}

// MAC over one 64-k chunk: xr[e] holds this chunk's k-pair (2*lane, 2*lane+1).
// Weights read as conflict-free LDS.128; x broadcast via shuffle (no crossbar).
#define CHUNK_MAC(NPAIRH)                                                        \
    _Pragma("unroll 4")                                                          \
    for (int mm = 0; mm < (NPAIRH); mm++){                                       \
        ulonglong2 w0 = wc0[cBase + mm];                                         \
        ulonglong2 w1 = wc1[cBase + mm];                                         \
        ulonglong2 w2 = wc2[cBase + mm];                                         \
        _Pragma("unroll")                                                        \
        for (int e = 0; e < EPB; e++){                                           \
            u64 xa = __shfl_sync(0xffffffffu, xr[e], 2*mm);                      \
            a0[e] = ffma2(xa, w0.x, a0[e]);                                      \
            a1[e] = ffma2(xa, w1.x, a1[e]);                                      \
            a2[e] = ffma2(xa, w2.x, a2[e]);                                      \
        }                                                                        \
        _Pragma("unroll")                                                        \
        for (int e = 0; e < EPB; e++){                                           \
            u64 xb = __shfl_sync(0xffffffffu, xr[e], 2*mm+1);                    \
            a0[e] = ffma2(xb, w0.y, a0[e]);                                      \
            a1[e] = ffma2(xb, w1.y, a1[e]);                                      \
            a2[e] = ffma2(xb, w2.y, a2[e]);                                      \
        }                                                                        \
    }

// ---------------- messages ----------------
__global__ __launch_bounds__(256,2)
void msg_kernel(const float* __restrict__ nodes, const float* __restrict__ efeat,
                const int* __restrict__ edges, const float* __restrict__ ew,
                const float* __restrict__ ed, const float* __restrict__ Wm,
                const float* __restrict__ bm, const float* __restrict__ gm,
                const float* __restrict__ betam, float* __restrict__ out_wm){
    extern __shared__ float smem[];
    float* sW  = smem;               // [96][KMP] col-major over k
    float* sb  = sW + FF*KMP;
    float* sg  = sb + FF;
    float* sbe = sg + FF;
    int tid = threadIdx.x;
    for (int i = tid; i < KM*FF; i += blockDim.x){
        int k = i / FF, c = i % FF;
        sW[c*KMP + k] = Wm[i];
    }
    if (tid < FF){ sb[tid]=bm[tid]; sg[tid]=gm[tid]; sbe[tid]=betam[tid]; }
    __syncthreads();

    int warp = tid >> 5, lane = tid & 31;
    int warpGlobal = blockIdx.x*8 + warp;

    const ulonglong2* wc0 = (const ulonglong2*)(sW + (size_t)lane*KMP);
    const ulonglong2* wc1 = (const ulonglong2*)(sW + (size_t)(lane+32)*KMP);
    const ulonglong2* wc2 = (const ulonglong2*)(sW + (size_t)(lane+64)*KMP);

    for (int base = warpGlobal*EPB; base < BB*EE; base += gridDim.x*8*EPB){
        int srcI[EPB], dstI[EPB];
        #pragma unroll
        for (int e = 0; e < EPB; e++){
            int eid = base + e;
            int b = eid >> 14;
            srcI[e] = (b << 10) + edges[2*eid];
            dstI[e] = (b << 10) + edges[2*eid+1];
        }

        u64 a0[EPB], a1[EPB], a2[EPB];
        #pragma unroll
        for (int e = 0; e < EPB; e++){ a0[e]=0ull; a1[e]=0ull; a2[e]=0ull; }

        u64 xr[EPB];
        int cBase;

        // chunk 0: k[0,64) = src[0,64)
        #pragma unroll
        for (int e = 0; e < EPB; e++)
            xr[e] = *(const u64*)(nodes + (size_t)srcI[e]*FF + 2*lane);
        cBase = 0;  CHUNK_MAC(16)

        // chunk 1: k[64,128) = src[64,96) | dst[0,32)
        #pragma unroll
        for (int e = 0; e < EPB; e++){
            int off = (lane < 16) ? (srcI[e]*FF + 64 + 2*lane)
                                  : (dstI[e]*FF + 2*(lane-16));
            xr[e] = *(const u64*)(nodes + (size_t)off);
        }
        cBase = 16; CHUNK_MAC(16)

        // chunk 2: k[128,192) = dst[32,96)
        #pragma unroll
        for (int e = 0; e < EPB; e++)
            xr[e] = *(const u64*)(nodes + (size_t)dstI[e]*FF + 32 + 2*lane);
        cBase = 32; CHUNK_MAC(16)

        // chunk 3: k[192,224) = efeat[0,32)  (only lanes 0..15 are shfl sources)
        #pragma unroll
        for (int e = 0; e < EPB; e++)
            xr[e] = *(const u64*)(efeat + (size_t)(base+e)*FE + 2*(lane & 15));
        cBase = 48; CHUNK_MAC(8)

        // epilogue: bias + GELU + LN + weight + store + scatter-add
        #pragma unroll
        for (int e = 0; e < EPB; e++){
            int eid = base + e;
            float v0 = gelu_erf(psum2(a0[e]) + sb[lane]);
            float v1 = gelu_erf(psum2(a1[e]) + sb[lane+32]);
            float v2 = gelu_erf(psum2(a2[e]) + sb[lane+64]);
            float s = v0 + v1 + v2;
            #pragma unroll
            for (int off = 16; off; off >>= 1) s += __shfl_xor_sync(0xffffffffu, s, off);
            float mu = s * (1.0f/96.0f);
            float d0 = v0-mu, d1 = v1-mu, d2 = v2-mu;
            float ssq = d0*d0 + d1*d1 + d2*d2;
            #pragma unroll
            for (int off = 16; off; off >>= 1) ssq += __shfl_xor_sync(0xffffffffu, ssq, off);
            float r = rsqrtf(ssq * (1.0f/96.0f) + LN_EPS);
            float w  = ew[eid];
            float dr = ed[2*eid+1];
            float y0 = (d0*r*sg[lane]    + sbe[lane])    * w;
            float y1 = (d1*r*sg[lane+32] + sbe[lane+32]) * w;
            float y2 = (d2*r*sg[lane+64] + sbe[lane+64]) * w;
            float* ow = out_wm + (size_t)eid*FF;
            ow[lane] = y0; ow[lane+32] = y1; ow[lane+64] = y2;
            float* ap = g_agg + (size_t)dstI[e]*FF;
            atomicAdd(ap+lane,    y0*dr);
            atomicAdd(ap+lane+32, y1*dr);
            atomicAdd(ap+lane+64, y2*dr);
        }
    }
}

// ---------------- q/k/v/gate projections (one matrix per blockIdx.y) ----------------
__global__ __launch_bounds__(256,2)
void qkvg_kernel(const float* __restrict__ nodes,
    const float* __restrict__ Wq, const float* __restrict__ bq,
    const float* __restrict__ Wk, const float* __restrict__ bk,
    const float* __restrict__ Wv, const float* __restrict__ bv,
    const float* __restrict__ Wg, const float* __restrict__ bg){
    extern __shared__ float smem[];
    float* sA  = smem;               // [96][K2P]
    float* sbA = sA + FF*K2P;
    int m = blockIdx.y;
    const float* WA = (m==0)?Wq:((m==1)?Wk:((m==2)?Wv:Wg));
    const float* bA = (m==0)?bq:((m==1)?bk:((m==2)?bv:bg));
    float* outA     = (m==0)?g_q:((m==1)?g_k:((m==2)?g_v:g_gate));
    bool isGate = (m == 3);

    int tid = threadIdx.x;
    for (int i = tid; i < K2*FF; i += blockDim.x){
        int k = i / FF, c = i % FF;
        sA[c*K2P + k] = WA[i];
    }
    if (tid < FF) sbA[tid] = bA[tid];
    __syncthreads();

    int warp = tid>>5, lane = tid&31;
    int warpGlobal = blockIdx.x*8 + warp;

    const ulonglong2* wc0 = (const ulonglong2*)(sA + (size_t)lane*K2P);
    const ulonglong2* wc1 = (const ulonglong2*)(sA + (size_t)(lane+32)*K2P);
    const ulonglong2* wc2 = (const ulonglong2*)(sA + (size_t)(lane+64)*K2P);

    for (int base = warpGlobal*EPB; base < BB*NN; base += gridDim.x*8*EPB){
        u64 a0[EPB], a1[EPB], a2[EPB];
        #pragma unroll
        for (int e = 0; e < EPB; e++){ a0[e]=0ull; a1[e]=0ull; a2[e]=0ull; }

        u64 xr[EPB];
        int cBase;

        // chunk 0: k[0,64) = nodes[0,64)
        #pragma unroll
        for (int e = 0; e < EPB; e++)
            xr[e] = *(const u64*)(nodes + (size_t)(base+e)*FF + 2*lane);
        cBase = 0;  CHUNK_MAC(16)

        // chunk 1: k[64,128) = nodes[64,96) | agg[0,32)
        #pragma unroll
        for (int e = 0; e < EPB; e++){
            const float* p = (lane < 16) ? (nodes + (size_t)(base+e)*FF + 64 + 2*lane)
                                         : (g_agg + (size_t)(base+e)*FF + 2*(lane-16));
            xr[e] = *(const u64*)p;
        }
        cBase = 16; CHUNK_MAC(16)

        // chunk 2: k[128,192) = agg[32,96)
        #pragma unroll
        for (int e = 0; e < EPB; e++)
            xr[e] = *(const u64*)(g_agg + (size_t)(base+e)*FF + 32 + 2*lane);
        cBase = 32; CHUNK_MAC(16)

        #pragma unroll
        for (int e = 0; e < EPB; e++){
            int idx = base + e;
            int b = idx >> 10, n = idx & (NN-1);
            float vals[3];
            vals[0] = psum2(a0[e]) + sbA[lane];
            vals[1] = psum2(a1[e]) + sbA[lane+32];
            vals[2] = psum2(a2[e]) + sbA[lane+64];
            #pragma unroll
            for (int c = 0; c < 3; c++){
                int col = lane + 32*c;
                int h = col >> 3, dl = col & 7;
                size_t off = ((size_t)(b*HH + h)*NN + n)*DD + dl;
                float v = vals[c];
                if (isGate) v = 1.0f/(1.0f + __expf(-v));
                outA[off] = v;
            }
        }
    }
}

// ---------------- attention: lane-local online softmax, 4 rows/warp, single K/V sweep ----------------
#define RPW 4
__global__ __launch_bounds__(256,2)
void attn_kernel(){
    extern __shared__ float smem[];
    float* sK = smem;                // [N][10] padded
    float* sV = smem + NN*10;
    int bh = blockIdx.x;
    int b = bh / HH, h = bh % HH;
    int tid = threadIdx.x;

    for (int j = tid; j < NN; j += 256){
        const ulonglong2* kr = (const ulonglong2*)(g_k + ((size_t)bh*NN + j)*DD);
        const ulonglong2* vr = (const ulonglong2*)(g_v + ((size_t)bh*NN + j)*DD);
        ulonglong2 k01 = kr[0], k23 = kr[1];
        ulonglong2 v01 = vr[0], v23 = vr[1];
        u64* kd = (u64*)(sK + (size_t)j*10);
        u64* vd = (u64*)(sV + (size_t)j*10);
        kd[0]=k01.x; kd[1]=k01.y; kd[2]=k23.x; kd[3]=k23.y;
        vd[0]=v01.x; vd[1]=v01.y; vd[2]=v23.x; vd[3]=v23.y;
    }
    __syncthreads();

    int warp = tid>>5, lane = tid&31;
    int rowBase = blockIdx.y*128 + warp*RPW;

    for (int p = 0; p < 4; p++){
        int r0 = rowBase + p*32;

        u64 q2[RPW][4];
        #pragma unroll
        for (int rr = 0; rr < RPW; rr++){
            const ulonglong2* qp = (const ulonglong2*)(g_q + ((size_t)bh*NN + r0+rr)*DD);
            ulonglong2 qa = qp[0], qb = qp[1];
            q2[rr][0]=qa.x; q2[rr][1]=qa.y; q2[rr][2]=qb.x; q2[rr][3]=qb.y;
        }

        float m[RPW], l[RPW];
        u64 o2[RPW][4];
        #pragma unroll
        for (int rr = 0; rr < RPW; rr++){
            m[rr] = -3.4e38f; l[rr] = 0.0f;
            o2[rr][0]=o2[rr][1]=o2[rr][2]=o2[rr][3]=0ull;
        }
        #pragma unroll 4
        for (int t = 0; t < 32; t++){
            int j = t*32 + lane;
            const u64* kj = (const u64*)(sK + (size_t)j*10);
            const u64* vj = (const u64*)(sV + (size_t)j*10);
            u64 k0=kj[0], k1=kj[1], k2=kj[2], k3=kj[3];
            u64 v0=vj[0], v1=vj[1], v2=vj[2], v3=vj[3];
            #pragma unroll
            for (int rr = 0; rr < RPW; rr++){
                u64 acc = fmul2(q2[rr][0], k0);
                acc = ffma2(q2[rr][1], k1, acc);
                acc = ffma2(q2[rr][2], k2, acc);
                acc = ffma2(q2[rr][3], k3, acc);
                float s = psum2(acc) * ATT_SCALE;
                float mn  = fmaxf(m[rr], s);
                float fac = __expf(m[rr] - mn);
                float pe  = __expf(s - mn);
                m[rr] = mn;
                l[rr] = l[rr]*fac + pe;
                u64 fc2 = pack2(fac, fac);
                u64 p2  = pack2(pe, pe);
                o2[rr][0] = ffma2(p2, v0, fmul2(fc2, o2[rr][0]));
                o2[rr][1] = ffma2(p2, v1, fmul2(fc2, o2[rr][1]));
                o2[rr][2] = ffma2(p2, v2, fmul2(fc2, o2[rr][2]));
                o2[rr][3] = ffma2(p2, v3, fmul2(fc2, o2[rr][3]));
            }
        }

        #pragma unroll
        for (int rr = 0; rr < RPW; rr++){
            float M = m[rr];
            #pragma unroll
            for (int off = 16; off; off >>= 1) M = fmaxf(M, __shfl_xor_sync(0xffffffffu, M, off));
            float fac = __expf(m[rr] - M);
            l[rr] *= fac;
            u64 fc2 = pack2(fac, fac);
            #pragma unroll
            for (int k = 0; k < 4; k++) o2[rr][k] = fmul2(fc2, o2[rr][k]);

            #pragma unroll
            for (int off = 16; off; off >>= 1) l[rr] += __shfl_xor_sync(0xffffffffu, l[rr], off);
            float2 od[4];
            #pragma unroll
            for (int k = 0; k < 4; k++){
                u64 v = o2[rr][k];
                #pragma unroll
                for (int off = 16; off; off >>= 1){
                    u64 o = __shfl_xor_sync(0xffffffffu, v, off);
                    float2 va = unpack2(v), vb = unpack2(o);
                    v = pack2(va.x+vb.x, va.y+vb.y);
                }
                od[k] = unpack2(v);
            }
            if (lane < DD){
                float inv = 1.0f / l[rr];
                float val = (lane & 1) ? od[lane>>1].y : od[lane>>1].x;
                float gate = g_gate[((size_t)bh*NN + r0+rr)*DD + lane];
                g_att[((size_t)((b<<10) + r0+rr))*FF + h*DD + lane] = val*inv*gate;
            }
        }
    }
}

// ---------------- output: LN(GELU(att @ Wo + bo)) ----------------
__global__ __launch_bounds__(512,1)
void out_kernel(const float* __restrict__ Wo, const float* __restrict__ bo,
                const float* __restrict__ gu, const float* __restrict__ betau,
                float* __restrict__ out){
    __shared__ float sW[FF*FF];
    __shared__ float sb[FF], sg[FF], sbe[FF];
    __shared__ float sx[16*FF];
    int tid = threadIdx.x;
    for (int i = tid; i < FF*FF; i += blockDim.x) sW[i] = Wo[i];
    if (tid < FF){ sb[tid]=bo[tid]; sg[tid]=gu[tid]; sbe[tid]=betau[tid]; }
    __syncthreads();

    int warp = tid>>5, lane = tid&31;
    float* x = sx + warp*FF;
    for (int idx = blockIdx.x*16 + warp; idx < BB*NN; idx += gridDim.x*16){
        const float* ap = g_att + (size_t)idx*FF;
        for (int i = lane; i < FF; i += 32) x[i] = ap[i];
        __syncwarp();
        float a0 = sb[lane], a1 = sb[lane+32], a2 = sb[lane+64];
        #pragma unroll 4
        for (int k = 0; k < FF; k++){
            float xv = x[k];
            a0 = fmaf(xv, sW[k*FF+lane],    a0);
            a1 = fmaf(xv, sW[k*FF+lane+32], a1);
            a2 = fmaf(xv, sW[k*FF+lane+64], a2);
        }
        a0 = gelu_erf(a0); a1 = gelu_erf(a1); a2 = gelu_erf(a2);
        float s = a0 + a1 + a2;
        #pragma unroll
        for (int off = 16; off; off >>= 1) s += __shfl_xor_sync(0xffffffffu, s, off);
        float mu = s * (1.0f/96.0f);
        float d0 = a0-mu, d1 = a1-mu, d2 = a2-mu;
        float ssq = d0*d0 + d1*d1 + d2*d2;
        #pragma unroll
        for (int off = 16; off; off >>= 1) ssq += __shfl_xor_sync(0xffffffffu, ssq, off);
        float r = rsqrtf(ssq * (1.0f/96.0f) + LN_EPS);
        float* op = out + (size_t)idx*FF;
        op[lane]    = d0*r*sg[lane]    + sbe[lane];
        op[lane+32] = d1*r*sg[lane+32] + sbe[lane+32];
        op[lane+64] = d2*r*sg[lane+64] + sbe[lane+64];
        __syncwarp();
    }
}

// ---------------- launch ----------------
extern "C" void kernel_launch(void* const* d_in, const int* in_sizes, int n_in,
                              void* d_out, int out_size){
    const float* nodes = (const float*)d_in[0];
    const float* efeat = (const float*)d_in[1];
    const int*   edges = (const int*)  d_in[2];
    const float* ew    = (const float*)d_in[3];
    const float* ed    = (const float*)d_in[4];
    const float* Wm    = (const float*)d_in[5];
    const float* bm    = (const float*)d_in[6];
    const float* gm    = (const float*)d_in[7];
    const float* betam = (const float*)d_in[8];
    const float* Wq=(const float*)d_in[9],  *bq=(const float*)d_in[10];
    const float* Wk=(const float*)d_in[11], *bk=(const float*)d_in[12];
    const float* Wv=(const float*)d_in[13], *bv=(const float*)d_in[14];
    const float* Wg=(const float*)d_in[15], *bg=(const float*)d_in[16];
    const float* Wo=(const float*)d_in[17], *bo=(const float*)d_in[18];
    const float* gu=(const float*)d_in[19], *betau=(const float*)d_in[20];
    float* out = (float*)d_out;

    const size_t OFF_WM    = (size_t)BB*NN*FF;
    const size_t OFF_EDGES = OFF_WM + (size_t)BB*EE*FF;
    const size_t OFF_EW    = OFF_EDGES + (size_t)BB*EE*2;
    const size_t OFF_ED    = OFF_EW + (size_t)BB*EE;

    const int MSG_SMEM  = (FF*KMP + 3*FF)*4;   // 88704 B (weights only)
    const int QKVG_SMEM = (FF*K2P + FF)*4;     // 75648 B
    const int ATTN_SMEM = 2*NN*10*4;           // 81920 B
    cudaFuncSetAttribute(msg_kernel,  cudaFuncAttributeMaxDynamicSharedMemorySize, MSG_SMEM);
    cudaFuncSetAttribute(qkvg_kernel, cudaFuncAttributeMaxDynamicSharedMemorySize, QKVG_SMEM);
    cudaFuncSetAttribute(attn_kernel, cudaFuncAttributeMaxDynamicSharedMemorySize, ATTN_SMEM);

    zero_agg_kernel<<<(BB*NN*FF+255)/256, 256>>>();
    passthrough_kernel<<<(BB*EE*2+255)/256, 256>>>(edges, ew, ed,
                                                   out+OFF_EDGES, out+OFF_EW, out+OFF_ED);
    msg_kernel<<<296, 256, MSG_SMEM>>>(nodes, efeat, edges, ew, ed,
                                       Wm, bm, gm, betam, out+OFF_WM);
    qkvg_kernel<<<dim3(64,4), 256, QKVG_SMEM>>>(nodes, Wq,bq, Wk,bk, Wv,bv, Wg,bg);
    attn_kernel<<<dim3(BB*HH,8), 256, ATTN_SMEM>>>();
    out_kernel<<<148, 512>>>(Wo, bo, gu, betau, out);
}

// round 9
// speedup vs baseline: 1.1998x; 1.1998x over previous
#include <cuda_runtime.h>
#include <cuda_bf16.h>
#include <math.h>
#include <stdint.h>

#define BB 8
#define NN 1024
#define EE 16384
#define FF 96
#define FE 32
#define HH 12
#define DD 8
#define KM 224
#define K2 192
#define K2P 196
#define EPB 8
#define WPB 16
#define LN_EPS 1e-3f
#define ATT_SCALE 0.35355339059327373f

typedef unsigned long long u64;

// ---------------- packed f32x2 helpers ----------------
__device__ __forceinline__ u64 ffma2(u64 a, u64 b, u64 c){
    u64 d; asm("fma.rn.f32x2 %0, %1, %2, %3;" : "=l"(d) : "l"(a), "l"(b), "l"(c)); return d;
}
__device__ __forceinline__ u64 fmul2(u64 a, u64 b){
    u64 d; asm("mul.rn.f32x2 %0, %1, %2;" : "=l"(d) : "l"(a), "l"(b)); return d;
}
__device__ __forceinline__ u64 pack2(float a, float b){
    u64 r; asm("mov.b64 %0, {%1, %2};" : "=l"(r) : "f"(a), "f"(b)); return r;
}
__device__ __forceinline__ float2 unpack2(u64 v){
    float2 f; asm("mov.b64 {%0, %1}, %2;" : "=f"(f.x), "=f"(f.y) : "l"(v)); return f;
}
__device__ __forceinline__ float psum2(u64 v){ float2 f = unpack2(v); return f.x + f.y; }

__device__ __forceinline__ float gelu_erf(float x){
    return 0.5f * x * (1.0f + erff(x * 0.70710678118654752f));
}

// ---------------- warp-mma helpers (baseline PTX, works on compute_103) ----------------
__device__ __forceinline__ uint32_t smem_u32(const void* p){
    uint32_t a;
    asm("{ .reg .u64 t; cvta.to.shared.u64 t, %1; cvt.u32.u64 %0, t; }" : "=r"(a) : "l"(p));
    return a;
}
__device__ __forceinline__ void ldsm4(uint32_t* r, uint32_t addr){
    asm volatile("ldmatrix.sync.aligned.m8n8.x4.shared.b16 {%0,%1,%2,%3}, [%4];"
        : "=r"(r[0]), "=r"(r[1]), "=r"(r[2]), "=r"(r[3]) : "r"(addr));
}
__device__ __forceinline__ void mma16816(float* d, const uint32_t* a, const uint32_t* b){
    asm volatile("mma.sync.aligned.m16n8k16.row.col.f32.bf16.bf16.f32 "
        "{%0,%1,%2,%3}, {%4,%5,%6,%7}, {%8,%9}, {%0,%1,%2,%3};"
        : "+f"(d[0]), "+f"(d[1]), "+f"(d[2]), "+f"(d[3])
        : "r"(a[0]), "r"(a[1]), "r"(a[2]), "r"(a[3]), "r"(b[0]), "r"(b[1]));
}
__device__ __forceinline__ void bf16_split2(float x0, float x1, uint32_t &h, uint32_t &l){
    asm("cvt.rn.bf16x2.f32 %0, %1, %2;" : "=r"(h) : "f"(x1), "f"(x0));
    float h0 = __uint_as_float(h << 16);
    float h1 = __uint_as_float(h & 0xffff0000u);
    float r0 = x0 - h0, r1 = x1 - h1;
    asm("cvt.rn.bf16x2.f32 %0, %1, %2;" : "=r"(l) : "f"(r1), "f"(r0));
}

// ---------------- scratch ----------------
__device__ float g_agg [BB*NN*FF];
__device__ float g_q   [BB*HH*NN*DD];
__device__ float g_k   [BB*HH*NN*DD];
__device__ float g_v   [BB*HH*NN*DD];
__device__ float g_gate[BB*HH*NN*DD];
__device__ float g_att [BB*NN*FF];

// ---------------- helpers ----------------
__global__ void zero_agg_kernel(){
    int i = blockIdx.x*blockDim.x + threadIdx.x;
    if (i < BB*NN*FF) g_agg[i] = 0.0f;
}

__global__ void passthrough_kernel(const int* __restrict__ edges,
                                   const float* __restrict__ ew,
                                   const float* __restrict__ ed,
                                   float* __restrict__ out_edges,
                                   float* __restrict__ out_ew,
                                   float* __restrict__ out_ed){
    int i = blockIdx.x*blockDim.x + threadIdx.x;
    if (i < BB*EE*2){ out_edges[i] = (float)edges[i]; out_ed[i] = ed[i]; }
    if (i < BB*EE)  out_ew[i] = ew[i];
}

// ================= message kernel: warp-mma bf16 hi/lo =================
// smem layout (bytes):
//   sSrc @0      [128] int
//   sDst @512    [128] int
//   bias @1024, gm @1408, be @1792 (96 floats each)
//   XH @2304  [128][232] bf16 = 59392 B
//   XL @61696
//   WH @121088 [96][232] bf16 = 44544 B
//   WL @165632                (end 210176)
#define XST 232
#define XRB (XST*2)          // 464-byte row stride
#define OFF_SRC  0
#define OFF_DST  512
#define OFF_BIAS 1024
#define OFF_GM   1408
#define OFF_BE   1792
#define OFF_XH   2304
#define OFF_XL   (OFF_XH + 128*XRB)
#define OFF_WH   (OFF_XL + 128*XRB)
#define OFF_WL   (OFF_WH + 96*XRB)
#define MSG_SMEM (OFF_WL + 96*XRB)
#define NTILES (BB*EE/128)   // 1024

__global__ __launch_bounds__(256,1)
void msg_mma_kernel(const float* __restrict__ nodes, const float* __restrict__ efeat,
                    const int* __restrict__ edges, const float* __restrict__ ew,
                    const float* __restrict__ ed, const float* __restrict__ Wm,
                    const float* __restrict__ bm, const float* __restrict__ gm,
                    const float* __restrict__ betam, float* __restrict__ out_wm){
    extern __shared__ char smem[];
    uint32_t sb = smem_u32(smem);
    int tid = threadIdx.x, wid = tid >> 5, lane = tid & 31;

    int* sSrc = (int*)(smem + OFF_SRC);
    int* sDst = (int*)(smem + OFF_DST);
    float* biasS = (float*)(smem + OFF_BIAS);
    float* gmS   = (float*)(smem + OFF_GM);
    float* beS   = (float*)(smem + OFF_BE);

    // stage W hi/lo transposed: sW[n][k]
    for (int idx = tid; idx < KM*FF; idx += 256){
        int k = idx / FF, n = idx % FF;
        float w = Wm[idx];
        __nv_bfloat16 hb = __float2bfloat16_rn(w);
        float hf = __bfloat162float(hb);
        __nv_bfloat16 lb = __float2bfloat16_rn(w - hf);
        *(__nv_bfloat16*)(smem + OFF_WH + n*XRB + k*2) = hb;
        *(__nv_bfloat16*)(smem + OFF_WL + n*XRB + k*2) = lb;
    }
    if (tid < FF){ biasS[tid] = bm[tid]; gmS[tid] = gm[tid]; beS[tid] = betam[tid]; }
    __syncthreads();

    // ldmatrix lane addresses
    // A (X): lanes 0-15 rows m0-15 @k+0, lanes 16-31 rows m0-15 @k+8
    uint32_t aRow = (uint32_t)(wid*16 + (lane & 15));
    uint32_t aOff = aRow*XRB + ((lane >> 4) * 16);
    uint32_t ah_base = sb + OFF_XH + aOff;
    uint32_t al_base = sb + OFF_XL + aOff;
    // B (W): lanes 0-7 rows n0-7 @k+0, 8-15 rows n0-7 @k+8, 16-23 rows n8-15 @k+0, 24-31 @k+8
    uint32_t bRow = (uint32_t)((lane & 7) + ((lane >> 4) & 1)*8);
    uint32_t bOff = bRow*XRB + (((lane >> 3) & 1) * 16);
    uint32_t wh_base = sb + OFF_WH + bOff;
    uint32_t wl_base = sb + OFF_WL + bOff;

    for (int tile = blockIdx.x; tile < NTILES; tile += gridDim.x){
        // ---- stage edge indices ----
        if (tid < 128){
            int eid = tile*128 + tid;
            int b = eid >> 14;
            sSrc[tid] = (b << 10) + edges[2*eid];
            sDst[tid] = (b << 10) + edges[2*eid+1];
        }
        __syncthreads();

        // ---- gather + bf16 split into XH/XL ----
        for (int ci = tid; ci < 128*28; ci += 256){
            int row = ci / 28;
            int kc  = (ci - row*28) * 8;
            const float* sp;
            if (kc < 96)       sp = nodes + (size_t)sSrc[row]*FF + kc;
            else if (kc < 192) sp = nodes + (size_t)sDst[row]*FF + (kc - 96);
            else               sp = efeat + (size_t)(tile*128 + row)*FE + (kc - 192);
            float4 f0 = ((const float4*)sp)[0];
            float4 f1 = ((const float4*)sp)[1];
            uint32_t h0,h1,h2,h3, l0,l1,l2,l3;
            bf16_split2(f0.x, f0.y, h0, l0);
            bf16_split2(f0.z, f0.w, h1, l1);
            bf16_split2(f1.x, f1.y, h2, l2);
            bf16_split2(f1.z, f1.w, h3, l3);
            int off = row*XRB + kc*2;
            *(uint4*)(smem + OFF_XH + off) = make_uint4(h0,h1,h2,h3);
            *(uint4*)(smem + OFF_XL + off) = make_uint4(l0,l1,l2,l3);
        }
        __syncthreads();

        // ---- MMA: warp owns m16 strip; 14 kt x 12 nt x 3 passes ----
        float d[12][4];
        #pragma unroll
        for (int nt = 0; nt < 12; nt++){ d[nt][0]=d[nt][1]=d[nt][2]=d[nt][3]=0.0f; }

        #pragma unroll 1
        for (int kt = 0; kt < 14; kt++){
            uint32_t Ah[4], Al[4], Bh[24], Bl[24];
            ldsm4(Ah, ah_base + kt*32);
            ldsm4(Al, al_base + kt*32);
            #pragma unroll
            for (int g = 0; g < 6; g++){
                ldsm4(&Bh[g*4], wh_base + g*16*XRB + kt*32);
                ldsm4(&Bl[g*4], wl_base + g*16*XRB + kt*32);
            }
            #pragma unroll
            for (int nt = 0; nt < 12; nt++){
                // x4 group g=nt/2: nt even -> regs 4g,4g+1 ; odd -> 4g+2,4g+3
                const uint32_t* bh = &Bh[(nt>>1)*4 + (nt&1)*2];
                const uint32_t* bl = &Bl[(nt>>1)*4 + (nt&1)*2];
                mma16816(d[nt], Ah, bh);
                mma16816(d[nt], Al, bh);
                mma16816(d[nt], Ah, bl);
            }
        }

        // ---- epilogue: lane holds rows (wid*16 + l/4) and (+8), 24 cols each ----
        #pragma unroll
        for (int j = 0; j < 2; j++){
            int row = wid*16 + (lane >> 2) + j*8;
            int eid = tile*128 + row;
            int c0 = 2*(lane & 3);

            float g[24];
            float s = 0.0f;
            #pragma unroll
            for (int nt = 0; nt < 12; nt++){
                int c = nt*8 + c0;
                float v0 = gelu_erf(d[nt][2*j]   + biasS[c]);
                float v1 = gelu_erf(d[nt][2*j+1] + biasS[c+1]);
                g[2*nt] = v0; g[2*nt+1] = v1;
                s += v0 + v1;
            }
            s += __shfl_xor_sync(0xffffffffu, s, 1);
            s += __shfl_xor_sync(0xffffffffu, s, 2);
            float mu = s * (1.0f/96.0f);
            float ssq = 0.0f;
            #pragma unroll
            for (int i = 0; i < 24; i++){ float dv = g[i]-mu; ssq += dv*dv; }
            ssq += __shfl_xor_sync(0xffffffffu, ssq, 1);
            ssq += __shfl_xor_sync(0xffffffffu, ssq, 2);
            float r = rsqrtf(ssq * (1.0f/96.0f) + LN_EPS);

            float w  = ew[eid];
            float dr = ed[2*eid+1];
            int dst  = sDst[row];
            float* ow = out_wm + (size_t)eid*FF;
            float* ap = g_agg + (size_t)dst*FF;
            #pragma unroll
            for (int nt = 0; nt < 12; nt++){
                int c = nt*8 + c0;
                float y0 = ((g[2*nt]  -mu)*r*gmS[c]   + beS[c])   * w;
                float y1 = ((g[2*nt+1]-mu)*r*gmS[c+1] + beS[c+1]) * w;
                *(float2*)(ow + c) = make_float2(y0, y1);
                atomicAdd(ap + c,     y0*dr);
                atomicAdd(ap + c + 1, y1*dr);
            }
        }
        __syncthreads();
    }
}

// ---------------- q/k/v/gate projections (R6 staged version) ----------------
__global__ __launch_bounds__(32*WPB,1)
void qkvg_kernel(const float* __restrict__ nodes,
    const float* __restrict__ Wq, const float* __restrict__ bq,
    const float* __restrict__ Wk, const float* __restrict__ bk,
    const float* __restrict__ Wv, const float* __restrict__ bv,
    const float* __restrict__ Wg, const float* __restrict__ bg){
    extern __shared__ float smemf[];
    float* sA  = smemf;
    float* sbA = sA + FF*K2P;
    float* sx  = sbA + FF;
    int m = blockIdx.y;
    const float* WA = (m==0)?Wq:((m==1)?Wk:((m==2)?Wv:Wg));
    const float* bA = (m==0)?bq:((m==1)?bk:((m==2)?bv:bg));
    float* outA     = (m==0)?g_q:((m==1)?g_k:((m==2)?g_v:g_gate));
    bool isGate = (m == 3);

    int tid = threadIdx.x;
    for (int i = tid; i < K2*FF; i += blockDim.x){
        int k = i / FF, c = i % FF;
        sA[c*K2P + k] = WA[i];
    }
    if (tid < FF) sbA[tid] = bA[tid];
    __syncthreads();

    int warp = tid>>5, lane = tid&31;
    float* x = sx + warp*(EPB*K2);
    int warpGlobal = blockIdx.x*WPB + warp;

    const ulonglong2* wp0 = (const ulonglong2*)(sA + (size_t)lane*K2P);
    const ulonglong2* wp1 = (const ulonglong2*)(sA + (size_t)(lane+32)*K2P);
    const ulonglong2* wp2 = (const ulonglong2*)(sA + (size_t)(lane+64)*K2P);

    for (int base = warpGlobal*EPB; base < BB*NN; base += gridDim.x*WPB*EPB){
        #pragma unroll
        for (int e = 0; e < EPB; e++){
            int idx = base + e;
            const float4* np = (const float4*)(nodes + (size_t)idx*FF);
            const float4* ap = (const float4*)(g_agg + (size_t)idx*FF);
            float4* xe = (float4*)(x + e*K2);
            #pragma unroll
            for (int i0 = 0; i0 < 2; i0++){
                int i = lane + 32*i0;
                if (i < 48){
                    float4 v = (i < 24) ? np[i] : ap[i-24];
                    xe[i] = v;
                }
            }
        }
        __syncwarp();

        u64 a0[EPB], a1[EPB], a2[EPB];
        #pragma unroll
        for (int e = 0; e < EPB; e++){ a0[e]=0ull; a1[e]=0ull; a2[e]=0ull; }

        #pragma unroll 4
        for (int ks = 0; ks < K2/4; ks++){
            ulonglong2 w0 = wp0[ks], w1 = wp1[ks], w2 = wp2[ks];
            #pragma unroll
            for (int e = 0; e < EPB; e++){
                ulonglong2 xv = ((const ulonglong2*)(x + e*K2))[ks];
                a0[e] = ffma2(xv.x, w0.x, a0[e]); a0[e] = ffma2(xv.y, w0.y, a0[e]);
                a1[e] = ffma2(xv.x, w1.x, a1[e]); a1[e] = ffma2(xv.y, w1.y, a1[e]);
                a2[e] = ffma2(xv.x, w2.x, a2[e]); a2[e] = ffma2(xv.y, w2.y, a2[e]);
            }
        }
        __syncwarp();

        #pragma unroll
        for (int e = 0; e < EPB; e++){
            int idx = base + e;
            int b = idx >> 10, n = idx & (NN-1);
            float vals[3];
            vals[0] = psum2(a0[e]) + sbA[lane];
            vals[1] = psum2(a1[e]) + sbA[lane+32];
            vals[2] = psum2(a2[e]) + sbA[lane+64];
            #pragma unroll
            for (int c = 0; c < 3; c++){
                int col = lane + 32*c;
                int h = col >> 3, dl = col & 7;
                size_t off = ((size_t)(b*HH + h)*NN + n)*DD + dl;
                float v = vals[c];
                if (isGate) v = 1.0f/(1.0f + __expf(-v));
                outA[off] = v;
            }
        }
        __syncwarp();
    }
}

// ---------------- attention (R6 online-softmax version) ----------------
#define RPW 4
__global__ __launch_bounds__(256,2)
void attn_kernel(){
    extern __shared__ float smemf[];
    float* sK = smemf;
    float* sV = smemf + NN*10;
    int bh = blockIdx.x;
    int b = bh / HH, h = bh % HH;
    int tid = threadIdx.x;

    for (int j = tid; j < NN; j += 256){
        const ulonglong2* kr = (const ulonglong2*)(g_k + ((size_t)bh*NN + j)*DD);
        const ulonglong2* vr = (const ulonglong2*)(g_v + ((size_t)bh*NN + j)*DD);
        ulonglong2 k01 = kr[0], k23 = kr[1];
        ulonglong2 v01 = vr[0], v23 = vr[1];
        u64* kd = (u64*)(sK + (size_t)j*10);
        u64* vd = (u64*)(sV + (size_t)j*10);
        kd[0]=k01.x; kd[1]=k01.y; kd[2]=k23.x; kd[3]=k23.y;
        vd[0]=v01.x; vd[1]=v01.y; vd[2]=v23.x; vd[3]=v23.y;
    }
    __syncthreads();

    int warp = tid>>5, lane = tid&31;
    int rowBase = blockIdx.y*128 + warp*RPW;

    for (int p = 0; p < 4; p++){
        int r0 = rowBase + p*32;

        u64 q2[RPW][4];
        #pragma unroll
        for (int rr = 0; rr < RPW; rr++){
            const ulonglong2* qp = (const ulonglong2*)(g_q + ((size_t)bh*NN + r0+rr)*DD);
            ulonglong2 qa = qp[0], qb = qp[1];
            q2[rr][0]=qa.x; q2[rr][1]=qa.y; q2[rr][2]=qb.x; q2[rr][3]=qb.y;
        }

        float m[RPW], l[RPW];
        u64 o2[RPW][4];
        #pragma unroll
        for (int rr = 0; rr < RPW; rr++){
            m[rr] = -3.4e38f; l[rr] = 0.0f;
            o2[rr][0]=o2[rr][1]=o2[rr][2]=o2[rr][3]=0ull;
        }
        #pragma unroll 4
        for (int t = 0; t < 32; t++){
            int j = t*32 + lane;
            const u64* kj = (const u64*)(sK + (size_t)j*10);
            const u64* vj = (const u64*)(sV + (size_t)j*10);
            u64 k0=kj[0], k1=kj[1], k2=kj[2], k3=kj[3];
            u64 v0=vj[0], v1=vj[1], v2=vj[2], v3=vj[3];
            #pragma unroll
            for (int rr = 0; rr < RPW; rr++){
                u64 acc = fmul2(q2[rr][0], k0);
                acc = ffma2(q2[rr][1], k1, acc);
                acc = ffma2(q2[rr][2], k2, acc);
                acc = ffma2(q2[rr][3], k3, acc);
                float s = psum2(acc) * ATT_SCALE;
                float mn  = fmaxf(m[rr], s);
                float fac = __expf(m[rr] - mn);
                float pe  = __expf(s - mn);
                m[rr] = mn;
                l[rr] = l[rr]*fac + pe;
                u64 fc2 = pack2(fac, fac);
                u64 p2  = pack2(pe, pe);
                o2[rr][0] = ffma2(p2, v0, fmul2(fc2, o2[rr][0]));
                o2[rr][1] = ffma2(p2, v1, fmul2(fc2, o2[rr][1]));
                o2[rr][2] = ffma2(p2, v2, fmul2(fc2, o2[rr][2]));
                o2[rr][3] = ffma2(p2, v3, fmul2(fc2, o2[rr][3]));
            }
        }

        #pragma unroll
        for (int rr = 0; rr < RPW; rr++){
            float M = m[rr];
            #pragma unroll
            for (int off = 16; off; off >>= 1) M = fmaxf(M, __shfl_xor_sync(0xffffffffu, M, off));
            float fac = __expf(m[rr] - M);
            l[rr] *= fac;
            u64 fc2 = pack2(fac, fac);
            #pragma unroll
            for (int k = 0; k < 4; k++) o2[rr][k] = fmul2(fc2, o2[rr][k]);

            #pragma unroll
            for (int off = 16; off; off >>= 1) l[rr] += __shfl_xor_sync(0xffffffffu, l[rr], off);
            float2 od[4];
            #pragma unroll
            for (int k = 0; k < 4; k++){
                u64 v = o2[rr][k];
                #pragma unroll
                for (int off = 16; off; off >>= 1){
                    u64 o = __shfl_xor_sync(0xffffffffu, v, off);
                    float2 va = unpack2(v), vb = unpack2(o);
                    v = pack2(va.x+vb.x, va.y+vb.y);
                }
                od[k] = unpack2(v);
            }
            if (lane < DD){
                float inv = 1.0f / l[rr];
                float val = (lane & 1) ? od[lane>>1].y : od[lane>>1].x;
                float gate = g_gate[((size_t)bh*NN + r0+rr)*DD + lane];
                g_att[((size_t)((b<<10) + r0+rr))*FF + h*DD + lane] = val*inv*gate;
            }
        }
    }
}

// ---------------- output: LN(GELU(att @ Wo + bo)) ----------------
__global__ __launch_bounds__(512,1)
void out_kernel(const float* __restrict__ Wo, const float* __restrict__ bo,
                const float* __restrict__ gu, const float* __restrict__ betau,
                float* __restrict__ out){
    __shared__ float sW[FF*FF];
    __shared__ float sb[FF], sg[FF], sbe[FF];
    __shared__ float sx[16*FF];
    int tid = threadIdx.x;
    for (int i = tid; i < FF*FF; i += blockDim.x) sW[i] = Wo[i];
    if (tid < FF){ sb[tid]=bo[tid]; sg[tid]=gu[tid]; sbe[tid]=betau[tid]; }
    __syncthreads();

    int warp = tid>>5, lane = tid&31;
    float* x = sx + warp*FF;
    for (int idx = blockIdx.x*16 + warp; idx < BB*NN; idx += gridDim.x*16){
        const float* ap = g_att + (size_t)idx*FF;
        for (int i = lane; i < FF; i += 32) x[i] = ap[i];
        __syncwarp();
        float a0 = sb[lane], a1 = sb[lane+32], a2 = sb[lane+64];
        #pragma unroll 4
        for (int k = 0; k < FF; k++){
            float xv = x[k];
            a0 = fmaf(xv, sW[k*FF+lane],    a0);
            a1 = fmaf(xv, sW[k*FF+lane+32], a1);
            a2 = fmaf(xv, sW[k*FF+lane+64], a2);
        }
        a0 = gelu_erf(a0); a1 = gelu_erf(a1); a2 = gelu_erf(a2);
        float s = a0 + a1 + a2;
        #pragma unroll
        for (int off = 16; off; off >>= 1) s += __shfl_xor_sync(0xffffffffu, s, off);
        float mu = s * (1.0f/96.0f);
        float d0 = a0-mu, d1 = a1-mu, d2 = a2-mu;
        float ssq = d0*d0 + d1*d1 + d2*d2;
        #pragma unroll
        for (int off = 16; off; off >>= 1) ssq += __shfl_xor_sync(0xffffffffu, ssq, off);
        float r = rsqrtf(ssq * (1.0f/96.0f) + LN_EPS);
        float* op = out + (size_t)idx*FF;
        op[lane]    = d0*r*sg[lane]    + sbe[lane];
        op[lane+32] = d1*r*sg[lane+32] + sbe[lane+32];
        op[lane+64] = d2*r*sg[lane+64] + sbe[lane+64];
        __syncwarp();
    }
}

// ---------------- launch ----------------
extern "C" void kernel_launch(void* const* d_in, const int* in_sizes, int n_in,
                              void* d_out, int out_size){
    const float* nodes = (const float*)d_in[0];
    const float* efeat = (const float*)d_in[1];
    const int*   edges = (const int*)  d_in[2];
    const float* ew    = (const float*)d_in[3];
    const float* ed    = (const float*)d_in[4];
    const float* Wm    = (const float*)d_in[5];
    const float* bm    = (const float*)d_in[6];
    const float* gm    = (const float*)d_in[7];
    const float* betam = (const float*)d_in[8];
    const float* Wq=(const float*)d_in[9],  *bq=(const float*)d_in[10];
    const float* Wk=(const float*)d_in[11], *bk=(const float*)d_in[12];
    const float* Wv=(const float*)d_in[13], *bv=(const float*)d_in[14];
    const float* Wg=(const float*)d_in[15], *bg=(const float*)d_in[16];
    const float* Wo=(const float*)d_in[17], *bo=(const float*)d_in[18];
    const float* gu=(const float*)d_in[19], *betau=(const float*)d_in[20];
    float* out = (float*)d_out;

    const size_t OFF_WM    = (size_t)BB*NN*FF;
    const size_t OFF_EDGES = OFF_WM + (size_t)BB*EE*FF;
    const size_t OFF_EW    = OFF_EDGES + (size_t)BB*EE*2;
    const size_t OFF_ED    = OFF_EW + (size_t)BB*EE;

    const int QKVG_SMEM = (FF*K2P + FF + WPB*EPB*K2)*4;     // 173952 B
    const int ATTN_SMEM = 2*NN*10*4;                        // 81920 B
    cudaFuncSetAttribute(msg_mma_kernel, cudaFuncAttributeMaxDynamicSharedMemorySize, MSG_SMEM);
    cudaFuncSetAttribute(qkvg_kernel,    cudaFuncAttributeMaxDynamicSharedMemorySize, QKVG_SMEM);
    cudaFuncSetAttribute(attn_kernel,    cudaFuncAttributeMaxDynamicSharedMemorySize, ATTN_SMEM);

    zero_agg_kernel<<<(BB*NN*FF+255)/256, 256>>>();
    passthrough_kernel<<<(BB*EE*2+255)/256, 256>>>(edges, ew, ed,
                                                   out+OFF_EDGES, out+OFF_EW, out+OFF_ED);
    msg_mma_kernel<<<148, 256, MSG_SMEM>>>(nodes, efeat, edges, ew, ed,
                                           Wm, bm, gm, betam, out+OFF_WM);
    qkvg_kernel<<<dim3(37,4), 32*WPB, QKVG_SMEM>>>(nodes, Wq,bq, Wk,bk, Wv,bv, Wg,bg);
    attn_kernel<<<dim3(BB*HH,8), 256, ATTN_SMEM>>>();
    out_kernel<<<148, 512>>>(Wo, bo, gu, betau, out);
}

// round 10
// speedup vs baseline: 1.4399x; 1.2001x over previous
#include <cuda_runtime.h>
#include <cuda_bf16.h>
#include <math.h>
#include <stdint.h>

#define BB 8
#define NN 1024
#define EE 16384
#define FF 96
#define FE 32
#define HH 12
#define DD 8
#define KM 224
#define K2 192
#define K2P 196
#define EPB 8
#define WPB 16
#define LN_EPS 1e-3f
#define ATT_SCALE 0.35355339059327373f

typedef unsigned long long u64;

// ---------------- packed f32x2 helpers ----------------
__device__ __forceinline__ u64 ffma2(u64 a, u64 b, u64 c){
    u64 d; asm("fma.rn.f32x2 %0, %1, %2, %3;" : "=l"(d) : "l"(a), "l"(b), "l"(c)); return d;
}
__device__ __forceinline__ u64 fmul2(u64 a, u64 b){
    u64 d; asm("mul.rn.f32x2 %0, %1, %2;" : "=l"(d) : "l"(a), "l"(b)); return d;
}
__device__ __forceinline__ u64 pack2(float a, float b){
    u64 r; asm("mov.b64 %0, {%1, %2};" : "=l"(r) : "f"(a), "f"(b)); return r;
}
__device__ __forceinline__ float2 unpack2(u64 v){
    float2 f; asm("mov.b64 {%0, %1}, %2;" : "=f"(f.x), "=f"(f.y) : "l"(v)); return f;
}
__device__ __forceinline__ float psum2(u64 v){ float2 f = unpack2(v); return f.x + f.y; }

__device__ __forceinline__ float gelu_erf(float x){
    return 0.5f * x * (1.0f + erff(x * 0.70710678118654752f));
}

// ---------------- warp-mma helpers ----------------
__device__ __forceinline__ uint32_t smem_u32(const void* p){
    uint32_t a;
    asm("{ .reg .u64 t; cvta.to.shared.u64 t, %1; cvt.u32.u64 %0, t; }" : "=r"(a) : "l"(p));
    return a;
}
__device__ __forceinline__ void ldsm4(uint32_t* r, uint32_t addr){
    asm volatile("ldmatrix.sync.aligned.m8n8.x4.shared.b16 {%0,%1,%2,%3}, [%4];"
        : "=r"(r[0]), "=r"(r[1]), "=r"(r[2]), "=r"(r[3]) : "r"(addr));
}
__device__ __forceinline__ void mma16816(float* d, const uint32_t* a, const uint32_t* b){
    asm volatile("mma.sync.aligned.m16n8k16.row.col.f32.bf16.bf16.f32 "
        "{%0,%1,%2,%3}, {%4,%5,%6,%7}, {%8,%9}, {%0,%1,%2,%3};"
        : "+f"(d[0]), "+f"(d[1]), "+f"(d[2]), "+f"(d[3])
        : "r"(a[0]), "r"(a[1]), "r"(a[2]), "r"(a[3]), "r"(b[0]), "r"(b[1]));
}
__device__ __forceinline__ void bf16_split2(float x0, float x1, uint32_t &h, uint32_t &l){
    asm("cvt.rn.bf16x2.f32 %0, %1, %2;" : "=r"(h) : "f"(x1), "f"(x0));
    float h0 = __uint_as_float(h << 16);
    float h1 = __uint_as_float(h & 0xffff0000u);
    float r0 = x0 - h0, r1 = x1 - h1;
    asm("cvt.rn.bf16x2.f32 %0, %1, %2;" : "=r"(l) : "f"(r1), "f"(r0));
}

// ---------------- scratch ----------------
__device__ float g_agg [BB*NN*FF];
__device__ float g_q   [BB*HH*NN*DD];
__device__ float g_k   [BB*HH*NN*DD];
__device__ float g_v   [BB*HH*NN*DD];
__device__ float g_gate[BB*HH*NN*DD];
__device__ float g_att [BB*NN*FF];

// ---------------- helpers ----------------
__global__ void zero_agg_kernel(){
    int i = blockIdx.x*blockDim.x + threadIdx.x;
    if (i < BB*NN*FF) g_agg[i] = 0.0f;
}

__global__ void passthrough_kernel(const int* __restrict__ edges,
                                   const float* __restrict__ ew,
                                   const float* __restrict__ ed,
                                   float* __restrict__ out_edges,
                                   float* __restrict__ out_ew,
                                   float* __restrict__ out_ed){
    int i = blockIdx.x*blockDim.x + threadIdx.x;
    if (i < BB*EE*2){ out_edges[i] = (float)edges[i]; out_ed[i] = ed[i]; }
    if (i < BB*EE)  out_ew[i] = ew[i];
}

// ================= message kernel: warp-mma, A-fragments direct from global =================
// smem: bias@1024, gm@1408, be@1792, WH@2304 [96][232]bf16, WL@46848 ; total 91392 B
#define XST 232
#define XRB (XST*2)
#define OFF_BIAS 1024
#define OFF_GM   1408
#define OFF_BE   1792
#define OFF_WH   2304
#define OFF_WL   (OFF_WH + 96*XRB)
#define MSG_SMEM (OFF_WL + 96*XRB)
#define NSTRIPS (BB*EE/16)    // 8192 strips of 16 edges

__global__ __launch_bounds__(256,2)
void msg_mma_kernel(const float* __restrict__ nodes, const float* __restrict__ efeat,
                    const int* __restrict__ edges, const float* __restrict__ ew,
                    const float* __restrict__ ed, const float* __restrict__ Wm,
                    const float* __restrict__ bm, const float* __restrict__ gm,
                    const float* __restrict__ betam, float* __restrict__ out_wm){
    extern __shared__ char smem[];
    uint32_t sb = smem_u32(smem);
    int tid = threadIdx.x, wid = tid >> 5, lane = tid & 31;

    float* biasS = (float*)(smem + OFF_BIAS);
    float* gmS   = (float*)(smem + OFF_GM);
    float* beS   = (float*)(smem + OFF_BE);

    // stage W hi/lo transposed: sW[n][k], row stride 464 B
    for (int idx = tid; idx < KM*FF; idx += 256){
        int k = idx / FF, n = idx % FF;
        float w = Wm[idx];
        __nv_bfloat16 hb = __float2bfloat16_rn(w);
        float hf = __bfloat162float(hb);
        __nv_bfloat16 lb = __float2bfloat16_rn(w - hf);
        *(__nv_bfloat16*)(smem + OFF_WH + n*XRB + k*2) = hb;
        *(__nv_bfloat16*)(smem + OFF_WL + n*XRB + k*2) = lb;
    }
    if (tid < FF){ biasS[tid] = bm[tid]; gmS[tid] = gm[tid]; beS[tid] = betam[tid]; }
    __syncthreads();

    // B (W) ldmatrix lane addressing (validated in R9)
    uint32_t bRow = (uint32_t)((lane & 7) + ((lane >> 4) & 1)*8);
    uint32_t bOff = bRow*XRB + (((lane >> 3) & 1) * 16);
    uint32_t wh_base = sb + OFF_WH + bOff;
    uint32_t wl_base = sb + OFF_WL + bOff;

    int kk = 2*(lane & 3);     // A-fragment k offset within k-tile

    for (int strip = blockIdx.x*8 + wid; strip < NSTRIPS; strip += gridDim.x*8){
        // per-lane edge rows: e0 = row (lane>>2), e1 = row +8
        int e0 = strip*16 + (lane >> 2);
        int e1 = e0 + 8;
        int2 ep0 = *(const int2*)(edges + 2*e0);
        int2 ep1 = *(const int2*)(edges + 2*e1);
        int b0 = e0 >> 14, b1 = e1 >> 14;
        const float* src0 = nodes + (size_t)((b0<<10) + ep0.x)*FF;
        const float* dst0 = nodes + (size_t)((b0<<10) + ep0.y)*FF;
        const float* src1 = nodes + (size_t)((b1<<10) + ep1.x)*FF;
        const float* dst1 = nodes + (size_t)((b1<<10) + ep1.y)*FF;
        const float* ef0  = efeat + (size_t)e0*FE;
        const float* ef1  = efeat + (size_t)e1*FE;

        float d[12][4];
        #pragma unroll
        for (int nt = 0; nt < 12; nt++){ d[nt][0]=d[nt][1]=d[nt][2]=d[nt][3]=0.0f; }

        #pragma unroll 1
        for (int kt = 0; kt < 14; kt++){
            const float *p0, *p1;
            if (kt < 6)      { int ko = kt*16;        p0 = src0 + ko; p1 = src1 + ko; }
            else if (kt < 12){ int ko = kt*16 - 96;   p0 = dst0 + ko; p1 = dst1 + ko; }
            else             { int ko = kt*16 - 192;  p0 = ef0  + ko; p1 = ef1  + ko; }
            float2 f0 = *(const float2*)(p0 + kk);
            float2 f1 = *(const float2*)(p1 + kk);
            float2 f2 = *(const float2*)(p0 + kk + 8);
            float2 f3 = *(const float2*)(p1 + kk + 8);
            uint32_t Ah[4], Al[4];
            bf16_split2(f0.x, f0.y, Ah[0], Al[0]);
            bf16_split2(f1.x, f1.y, Ah[1], Al[1]);
            bf16_split2(f2.x, f2.y, Ah[2], Al[2]);
            bf16_split2(f3.x, f3.y, Ah[3], Al[3]);

            #pragma unroll
            for (int g = 0; g < 6; g++){
                uint32_t Bh[4], Bl[4];
                ldsm4(Bh, wh_base + (uint32_t)(g*16*XRB) + kt*32);
                ldsm4(Bl, wl_base + (uint32_t)(g*16*XRB) + kt*32);
                mma16816(d[2*g],   Ah, Bh);     mma16816(d[2*g],   Al, Bh);     mma16816(d[2*g],   Ah, Bl);
                mma16816(d[2*g+1], Ah, Bh+2);   mma16816(d[2*g+1], Al, Bh+2);   mma16816(d[2*g+1], Ah, Bl+2);
            }
        }

        // ---- epilogue: j=0 -> row e0 (d[][0..1]), j=1 -> row e1 (d[][2..3]) ----
        #pragma unroll
        for (int j = 0; j < 2; j++){
            int eid = j ? e1 : e0;
            int dstI = j ? ((b1<<10) + ep1.y) : ((b0<<10) + ep0.y);
            int c0 = kk;

            float g[24];
            float s = 0.0f;
            #pragma unroll
            for (int nt = 0; nt < 12; nt++){
                int c = nt*8 + c0;
                float v0 = gelu_erf(d[nt][2*j]   + biasS[c]);
                float v1 = gelu_erf(d[nt][2*j+1] + biasS[c+1]);
                g[2*nt] = v0; g[2*nt+1] = v1;
                s += v0 + v1;
            }
            s += __shfl_xor_sync(0xffffffffu, s, 1);
            s += __shfl_xor_sync(0xffffffffu, s, 2);
            float mu = s * (1.0f/96.0f);
            float ssq = 0.0f;
            #pragma unroll
            for (int i = 0; i < 24; i++){ float dv = g[i]-mu; ssq += dv*dv; }
            ssq += __shfl_xor_sync(0xffffffffu, ssq, 1);
            ssq += __shfl_xor_sync(0xffffffffu, ssq, 2);
            float r = rsqrtf(ssq * (1.0f/96.0f) + LN_EPS);

            float w  = ew[eid];
            float dr = ed[2*eid+1];
            float* ow = out_wm + (size_t)eid*FF;
            float* ap = g_agg + (size_t)dstI*FF;
            #pragma unroll
            for (int nt = 0; nt < 12; nt++){
                int c = nt*8 + c0;
                float y0 = ((g[2*nt]  -mu)*r*gmS[c]   + beS[c])   * w;
                float y1 = ((g[2*nt+1]-mu)*r*gmS[c+1] + beS[c+1]) * w;
                *(float2*)(ow + c) = make_float2(y0, y1);
                atomicAdd(ap + c,     y0*dr);
                atomicAdd(ap + c + 1, y1*dr);
            }
        }
    }
}

// ---------------- q/k/v/gate projections (R6 staged version) ----------------
__global__ __launch_bounds__(32*WPB,1)
void qkvg_kernel(const float* __restrict__ nodes,
    const float* __restrict__ Wq, const float* __restrict__ bq,
    const float* __restrict__ Wk, const float* __restrict__ bk,
    const float* __restrict__ Wv, const float* __restrict__ bv,
    const float* __restrict__ Wg, const float* __restrict__ bg){
    extern __shared__ float smemf[];
    float* sA  = smemf;
    float* sbA = sA + FF*K2P;
    float* sx  = sbA + FF;
    int m = blockIdx.y;
    const float* WA = (m==0)?Wq:((m==1)?Wk:((m==2)?Wv:Wg));
    const float* bA = (m==0)?bq:((m==1)?bk:((m==2)?bv:bg));
    float* outA     = (m==0)?g_q:((m==1)?g_k:((m==2)?g_v:g_gate));
    bool isGate = (m == 3);

    int tid = threadIdx.x;
    for (int i = tid; i < K2*FF; i += blockDim.x){
        int k = i / FF, c = i % FF;
        sA[c*K2P + k] = WA[i];
    }
    if (tid < FF) sbA[tid] = bA[tid];
    __syncthreads();

    int warp = tid>>5, lane = tid&31;
    float* x = sx + warp*(EPB*K2);
    int warpGlobal = blockIdx.x*WPB + warp;

    const ulonglong2* wp0 = (const ulonglong2*)(sA + (size_t)lane*K2P);
    const ulonglong2* wp1 = (const ulonglong2*)(sA + (size_t)(lane+32)*K2P);
    const ulonglong2* wp2 = (const ulonglong2*)(sA + (size_t)(lane+64)*K2P);

    for (int base = warpGlobal*EPB; base < BB*NN; base += gridDim.x*WPB*EPB){
        #pragma unroll
        for (int e = 0; e < EPB; e++){
            int idx = base + e;
            const float4* np = (const float4*)(nodes + (size_t)idx*FF);
            const float4* ap = (const float4*)(g_agg + (size_t)idx*FF);
            float4* xe = (float4*)(x + e*K2);
            #pragma unroll
            for (int i0 = 0; i0 < 2; i0++){
                int i = lane + 32*i0;
                if (i < 48){
                    float4 v = (i < 24) ? np[i] : ap[i-24];
                    xe[i] = v;
                }
            }
        }
        __syncwarp();

        u64 a0[EPB], a1[EPB], a2[EPB];
        #pragma unroll
        for (int e = 0; e < EPB; e++){ a0[e]=0ull; a1[e]=0ull; a2[e]=0ull; }

        #pragma unroll 4
        for (int ks = 0; ks < K2/4; ks++){
            ulonglong2 w0 = wp0[ks], w1 = wp1[ks], w2 = wp2[ks];
            #pragma unroll
            for (int e = 0; e < EPB; e++){
                ulonglong2 xv = ((const ulonglong2*)(x + e*K2))[ks];
                a0[e] = ffma2(xv.x, w0.x, a0[e]); a0[e] = ffma2(xv.y, w0.y, a0[e]);
                a1[e] = ffma2(xv.x, w1.x, a1[e]); a1[e] = ffma2(xv.y, w1.y, a1[e]);
                a2[e] = ffma2(xv.x, w2.x, a2[e]); a2[e] = ffma2(xv.y, w2.y, a2[e]);
            }
        }
        __syncwarp();

        #pragma unroll
        for (int e = 0; e < EPB; e++){
            int idx = base + e;
            int b = idx >> 10, n = idx & (NN-1);
            float vals[3];
            vals[0] = psum2(a0[e]) + sbA[lane];
            vals[1] = psum2(a1[e]) + sbA[lane+32];
            vals[2] = psum2(a2[e]) + sbA[lane+64];
            #pragma unroll
            for (int c = 0; c < 3; c++){
                int col = lane + 32*c;
                int h = col >> 3, dl = col & 7;
                size_t off = ((size_t)(b*HH + h)*NN + n)*DD + dl;
                float v = vals[c];
                if (isGate) v = 1.0f/(1.0f + __expf(-v));
                outA[off] = v;
            }
        }
        __syncwarp();
    }
}

// ---------------- attention (R6 online-softmax version) ----------------
#define RPW 4
__global__ __launch_bounds__(256,2)
void attn_kernel(){
    extern __shared__ float smemf[];
    float* sK = smemf;
    float* sV = smemf + NN*10;
    int bh = blockIdx.x;
    int b = bh / HH, h = bh % HH;
    int tid = threadIdx.x;

    for (int j = tid; j < NN; j += 256){
        const ulonglong2* kr = (const ulonglong2*)(g_k + ((size_t)bh*NN + j)*DD);
        const ulonglong2* vr = (const ulonglong2*)(g_v + ((size_t)bh*NN + j)*DD);
        ulonglong2 k01 = kr[0], k23 = kr[1];
        ulonglong2 v01 = vr[0], v23 = vr[1];
        u64* kd = (u64*)(sK + (size_t)j*10);
        u64* vd = (u64*)(sV + (size_t)j*10);
        kd[0]=k01.x; kd[1]=k01.y; kd[2]=k23.x; kd[3]=k23.y;
        vd[0]=v01.x; vd[1]=v01.y; vd[2]=v23.x; vd[3]=v23.y;
    }
    __syncthreads();

    int warp = tid>>5, lane = tid&31;
    int rowBase = blockIdx.y*128 + warp*RPW;

    for (int p = 0; p < 4; p++){
        int r0 = rowBase + p*32;

        u64 q2[RPW][4];
        #pragma unroll
        for (int rr = 0; rr < RPW; rr++){
            const ulonglong2* qp = (const ulonglong2*)(g_q + ((size_t)bh*NN + r0+rr)*DD);
            ulonglong2 qa = qp[0], qb = qp[1];
            q2[rr][0]=qa.x; q2[rr][1]=qa.y; q2[rr][2]=qb.x; q2[rr][3]=qb.y;
        }

        float m[RPW], l[RPW];
        u64 o2[RPW][4];
        #pragma unroll
        for (int rr = 0; rr < RPW; rr++){
            m[rr] = -3.4e38f; l[rr] = 0.0f;
            o2[rr][0]=o2[rr][1]=o2[rr][2]=o2[rr][3]=0ull;
        }
        #pragma unroll 4
        for (int t = 0; t < 32; t++){
            int j = t*32 + lane;
            const u64* kj = (const u64*)(sK + (size_t)j*10);
            const u64* vj = (const u64*)(sV + (size_t)j*10);
            u64 k0=kj[0], k1=kj[1], k2=kj[2], k3=kj[3];
            u64 v0=vj[0], v1=vj[1], v2=vj[2], v3=vj[3];
            #pragma unroll
            for (int rr = 0; rr < RPW; rr++){
                u64 acc = fmul2(q2[rr][0], k0);
                acc = ffma2(q2[rr][1], k1, acc);
                acc = ffma2(q2[rr][2], k2, acc);
                acc = ffma2(q2[rr][3], k3, acc);
                float s = psum2(acc) * ATT_SCALE;
                float mn  = fmaxf(m[rr], s);
                float fac = __expf(m[rr] - mn);
                float pe  = __expf(s - mn);
                m[rr] = mn;
                l[rr] = l[rr]*fac + pe;
                u64 fc2 = pack2(fac, fac);
                u64 p2  = pack2(pe, pe);
                o2[rr][0] = ffma2(p2, v0, fmul2(fc2, o2[rr][0]));
                o2[rr][1] = ffma2(p2, v1, fmul2(fc2, o2[rr][1]));
                o2[rr][2] = ffma2(p2, v2, fmul2(fc2, o2[rr][2]));
                o2[rr][3] = ffma2(p2, v3, fmul2(fc2, o2[rr][3]));
            }
        }

        #pragma unroll
        for (int rr = 0; rr < RPW; rr++){
            float M = m[rr];
            #pragma unroll
            for (int off = 16; off; off >>= 1) M = fmaxf(M, __shfl_xor_sync(0xffffffffu, M, off));
            float fac = __expf(m[rr] - M);
            l[rr] *= fac;
            u64 fc2 = pack2(fac, fac);
            #pragma unroll
            for (int k = 0; k < 4; k++) o2[rr][k] = fmul2(fc2, o2[rr][k]);

            #pragma unroll
            for (int off = 16; off; off >>= 1) l[rr] += __shfl_xor_sync(0xffffffffu, l[rr], off);
            float2 od[4];
            #pragma unroll
            for (int k = 0; k < 4; k++){
                u64 v = o2[rr][k];
                #pragma unroll
                for (int off = 16; off; off >>= 1){
                    u64 o = __shfl_xor_sync(0xffffffffu, v, off);
                    float2 va = unpack2(v), vb = unpack2(o);
                    v = pack2(va.x+vb.x, va.y+vb.y);
                }
                od[k] = unpack2(v);
            }
            if (lane < DD){
                float inv = 1.0f / l[rr];
                float val = (lane & 1) ? od[lane>>1].y : od[lane>>1].x;
                float gate = g_gate[((size_t)bh*NN + r0+rr)*DD + lane];
                g_att[((size_t)((b<<10) + r0+rr))*FF + h*DD + lane] = val*inv*gate;
            }
        }
    }
}

// ---------------- output: LN(GELU(att @ Wo + bo)) ----------------
__global__ __launch_bounds__(512,1)
void out_kernel(const float* __restrict__ Wo, const float* __restrict__ bo,
                const float* __restrict__ gu, const float* __restrict__ betau,
                float* __restrict__ out){
    __shared__ float sW[FF*FF];
    __shared__ float sb[FF], sg[FF], sbe[FF];
    __shared__ float sx[16*FF];
    int tid = threadIdx.x;
    for (int i = tid; i < FF*FF; i += blockDim.x) sW[i] = Wo[i];
    if (tid < FF){ sb[tid]=bo[tid]; sg[tid]=gu[tid]; sbe[tid]=betau[tid]; }
    __syncthreads();

    int warp = tid>>5, lane = tid&31;
    float* x = sx + warp*FF;
    for (int idx = blockIdx.x*16 + warp; idx < BB*NN; idx += gridDim.x*16){
        const float* ap = g_att + (size_t)idx*FF;
        for (int i = lane; i < FF; i += 32) x[i] = ap[i];
        __syncwarp();
        float a0 = sb[lane], a1 = sb[lane+32], a2 = sb[lane+64];
        #pragma unroll 4
        for (int k = 0; k < FF; k++){
            float xv = x[k];
            a0 = fmaf(xv, sW[k*FF+lane],    a0);
            a1 = fmaf(xv, sW[k*FF+lane+32], a1);
            a2 = fmaf(xv, sW[k*FF+lane+64], a2);
        }
        a0 = gelu_erf(a0); a1 = gelu_erf(a1); a2 = gelu_erf(a2);
        float s = a0 + a1 + a2;
        #pragma unroll
        for (int off = 16; off; off >>= 1) s += __shfl_xor_sync(0xffffffffu, s, off);
        float mu = s * (1.0f/96.0f);
        float d0 = a0-mu, d1 = a1-mu, d2 = a2-mu;
        float ssq = d0*d0 + d1*d1 + d2*d2;
        #pragma unroll
        for (int off = 16; off; off >>= 1) ssq += __shfl_xor_sync(0xffffffffu, ssq, off);
        float r = rsqrtf(ssq * (1.0f/96.0f) + LN_EPS);
        float* op = out + (size_t)idx*FF;
        op[lane]    = d0*r*sg[lane]    + sbe[lane];
        op[lane+32] = d1*r*sg[lane+32] + sbe[lane+32];
        op[lane+64] = d2*r*sg[lane+64] + sbe[lane+64];
        __syncwarp();
    }
}

// ---------------- launch ----------------
extern "C" void kernel_launch(void* const* d_in, const int* in_sizes, int n_in,
                              void* d_out, int out_size){
    const float* nodes = (const float*)d_in[0];
    const float* efeat = (const float*)d_in[1];
    const int*   edges = (const int*)  d_in[2];
    const float* ew    = (const float*)d_in[3];
    const float* ed    = (const float*)d_in[4];
    const float* Wm    = (const float*)d_in[5];
    const float* bm    = (const float*)d_in[6];
    const float* gm    = (const float*)d_in[7];
    const float* betam = (const float*)d_in[8];
    const float* Wq=(const float*)d_in[9],  *bq=(const float*)d_in[10];
    const float* Wk=(const float*)d_in[11], *bk=(const float*)d_in[12];
    const float* Wv=(const float*)d_in[13], *bv=(const float*)d_in[14];
    const float* Wg=(const float*)d_in[15], *bg=(const float*)d_in[16];
    const float* Wo=(const float*)d_in[17], *bo=(const float*)d_in[18];
    const float* gu=(const float*)d_in[19], *betau=(const float*)d_in[20];
    float* out = (float*)d_out;

    const size_t OFF_WM    = (size_t)BB*NN*FF;
    const size_t OFF_EDGES = OFF_WM + (size_t)BB*EE*FF;
    const size_t OFF_EW    = OFF_EDGES + (size_t)BB*EE*2;
    const size_t OFF_ED    = OFF_EW + (size_t)BB*EE;

    const int QKVG_SMEM = (FF*K2P + FF + WPB*EPB*K2)*4;     // 173952 B
    const int ATTN_SMEM = 2*NN*10*4;                        // 81920 B
    cudaFuncSetAttribute(msg_mma_kernel, cudaFuncAttributeMaxDynamicSharedMemorySize, MSG_SMEM);
    cudaFuncSetAttribute(qkvg_kernel,    cudaFuncAttributeMaxDynamicSharedMemorySize, QKVG_SMEM);
    cudaFuncSetAttribute(attn_kernel,    cudaFuncAttributeMaxDynamicSharedMemorySize, ATTN_SMEM);

    zero_agg_kernel<<<(BB*NN*FF+255)/256, 256>>>();
    passthrough_kernel<<<(BB*EE*2+255)/256, 256>>>(edges, ew, ed,
                                                   out+OFF_EDGES, out+OFF_EW, out+OFF_ED);
    msg_mma_kernel<<<296, 256, MSG_SMEM>>>(nodes, efeat, edges, ew, ed,
                                           Wm, bm, gm, betam, out+OFF_WM);
    qkvg_kernel<<<dim3(37,4), 32*WPB, QKVG_SMEM>>>(nodes, Wq,bq, Wk,bk, Wv,bv, Wg,bg);
    attn_kernel<<<dim3(BB*HH,8), 256, ATTN_SMEM>>>();
    out_kernel<<<148, 512>>>(Wo, bo, gu, betau, out);
}

// round 12
// speedup vs baseline: 2.1160x; 1.4695x over previous
#include <cuda_runtime.h>
#include <cuda_bf16.h>
#include <math.h>
#include <stdint.h>

#define BB 8
#define NN 1024
#define EE 16384
#define FF 96
#define FE 32
#define HH 12
#define DD 8
#define KM 224
#define K2 192
#define K2P 196
#define EPB 8
#define WPB 16
#define LN_EPS 1e-3f
#define ATT_SCALE 0.35355339059327373f

typedef unsigned long long u64;

// ---------------- packed f32x2 helpers ----------------
__device__ __forceinline__ u64 ffma2(u64 a, u64 b, u64 c){
    u64 d; asm("fma.rn.f32x2 %0, %1, %2, %3;" : "=l"(d) : "l"(a), "l"(b), "l"(c)); return d;
}
__device__ __forceinline__ u64 pack2(float a, float b){
    u64 r; asm("mov.b64 %0, {%1, %2};" : "=l"(r) : "f"(a), "f"(b)); return r;
}
__device__ __forceinline__ float2 unpack2(u64 v){
    float2 f; asm("mov.b64 {%0, %1}, %2;" : "=f"(f.x), "=f"(f.y) : "l"(v)); return f;
}
__device__ __forceinline__ float psum2(u64 v){ float2 f = unpack2(v); return f.x + f.y; }

__device__ __forceinline__ float gelu_erf(float x){
    return 0.5f * x * (1.0f + erff(x * 0.70710678118654752f));
}

// ---------------- warp-mma helpers ----------------
__device__ __forceinline__ uint32_t smem_u32(const void* p){
    uint32_t a;
    asm("{ .reg .u64 t; cvta.to.shared.u64 t, %1; cvt.u32.u64 %0, t; }" : "=r"(a) : "l"(p));
    return a;
}
__device__ __forceinline__ void ldsm4(uint32_t* r, uint32_t addr){
    asm volatile("ldmatrix.sync.aligned.m8n8.x4.shared.b16 {%0,%1,%2,%3}, [%4];"
        : "=r"(r[0]), "=r"(r[1]), "=r"(r[2]), "=r"(r[3]) : "r"(addr));
}
__device__ __forceinline__ void mma16816(float* d, const uint32_t* a, const uint32_t* b){
    asm volatile("mma.sync.aligned.m16n8k16.row.col.f32.bf16.bf16.f32 "
        "{%0,%1,%2,%3}, {%4,%5,%6,%7}, {%8,%9}, {%0,%1,%2,%3};"
        : "+f"(d[0]), "+f"(d[1]), "+f"(d[2]), "+f"(d[3])
        : "r"(a[0]), "r"(a[1]), "r"(a[2]), "r"(a[3]), "r"(b[0]), "r"(b[1]));
}
__device__ __forceinline__ void mma1688(float* d, const uint32_t* a, uint32_t b){
    asm volatile("mma.sync.aligned.m16n8k8.row.col.f32.bf16.bf16.f32 "
        "{%0,%1,%2,%3}, {%4,%5}, {%6}, {%0,%1,%2,%3};"
        : "+f"(d[0]), "+f"(d[1]), "+f"(d[2]), "+f"(d[3])
        : "r"(a[0]), "r"(a[1]), "r"(b));
}
__device__ __forceinline__ void bf16_split2(float x0, float x1, uint32_t &h, uint32_t &l){
    asm("cvt.rn.bf16x2.f32 %0, %1, %2;" : "=r"(h) : "f"(x1), "f"(x0));
    float h0 = __uint_as_float(h << 16);
    float h1 = __uint_as_float(h & 0xffff0000u);
    float r0 = x0 - h0, r1 = x1 - h1;
    asm("cvt.rn.bf16x2.f32 %0, %1, %2;" : "=r"(l) : "f"(r1), "f"(r0));
}

// ---------------- scratch ----------------
__device__ float g_agg [BB*NN*FF];
__device__ float g_q   [BB*HH*NN*DD];
__device__ float g_k   [BB*HH*NN*DD];
__device__ float g_v   [BB*HH*NN*DD];
__device__ float g_gate[BB*HH*NN*DD];
__device__ float g_att [BB*NN*FF];

// ---------------- helpers ----------------
__global__ void zero_agg_kernel(){
    int i = blockIdx.x*blockDim.x + threadIdx.x;
    if (i < BB*NN*FF) g_agg[i] = 0.0f;
}

__global__ void passthrough_kernel(const int* __restrict__ edges,
                                   const float* __restrict__ ew,
                                   const float* __restrict__ ed,
                                   float* __restrict__ out_edges,
                                   float* __restrict__ out_ew,
                                   float* __restrict__ out_ed){
    int i = blockIdx.x*blockDim.x + threadIdx.x;
    if (i < BB*EE*2){ out_edges[i] = (float)edges[i]; out_ed[i] = ed[i]; }
    if (i < BB*EE)  out_ew[i] = ew[i];
}

// ================= message kernel (R10 winner, unchanged) =================
#define XST 232
#define XRB (XST*2)
#define OFF_BIAS 1024
#define OFF_GM   1408
#define OFF_BE   1792
#define OFF_WH   2304
#define OFF_WL   (OFF_WH + 96*XRB)
#define MSG_SMEM (OFF_WL + 96*XRB)
#define NSTRIPS (BB*EE/16)

__global__ __launch_bounds__(256,2)
void msg_mma_kernel(const float* __restrict__ nodes, const float* __restrict__ efeat,
                    const int* __restrict__ edges, const float* __restrict__ ew,
                    const float* __restrict__ ed, const float* __restrict__ Wm,
                    const float* __restrict__ bm, const float* __restrict__ gm,
                    const float* __restrict__ betam, float* __restrict__ out_wm){
    extern __shared__ char smem[];
    uint32_t sb = smem_u32(smem);
    int tid = threadIdx.x, wid = tid >> 5, lane = tid & 31;

    float* biasS = (float*)(smem + OFF_BIAS);
    float* gmS   = (float*)(smem + OFF_GM);
    float* beS   = (float*)(smem + OFF_BE);

    for (int idx = tid; idx < KM*FF; idx += 256){
        int k = idx / FF, n = idx % FF;
        float w = Wm[idx];
        __nv_bfloat16 hb = __float2bfloat16_rn(w);
        float hf = __bfloat162float(hb);
        __nv_bfloat16 lb = __float2bfloat16_rn(w - hf);
        *(__nv_bfloat16*)(smem + OFF_WH + n*XRB + k*2) = hb;
        *(__nv_bfloat16*)(smem + OFF_WL + n*XRB + k*2) = lb;
    }
    if (tid < FF){ biasS[tid] = bm[tid]; gmS[tid] = gm[tid]; beS[tid] = betam[tid]; }
    __syncthreads();

    uint32_t bRow = (uint32_t)((lane & 7) + ((lane >> 4) & 1)*8);
    uint32_t bOff = bRow*XRB + (((lane >> 3) & 1) * 16);
    uint32_t wh_base = sb + OFF_WH + bOff;
    uint32_t wl_base = sb + OFF_WL + bOff;

    int kk = 2*(lane & 3);

    for (int strip = blockIdx.x*8 + wid; strip < NSTRIPS; strip += gridDim.x*8){
        int e0 = strip*16 + (lane >> 2);
        int e1 = e0 + 8;
        int2 ep0 = *(const int2*)(edges + 2*e0);
        int2 ep1 = *(const int2*)(edges + 2*e1);
        int b0 = e0 >> 14, b1 = e1 >> 14;
        const float* src0 = nodes + (size_t)((b0<<10) + ep0.x)*FF;
        const float* dst0 = nodes + (size_t)((b0<<10) + ep0.y)*FF;
        const float* src1 = nodes + (size_t)((b1<<10) + ep1.x)*FF;
        const float* dst1 = nodes + (size_t)((b1<<10) + ep1.y)*FF;
        const float* ef0  = efeat + (size_t)e0*FE;
        const float* ef1  = efeat + (size_t)e1*FE;

        float d[12][4];
        #pragma unroll
        for (int nt = 0; nt < 12; nt++){ d[nt][0]=d[nt][1]=d[nt][2]=d[nt][3]=0.0f; }

        #pragma unroll 1
        for (int kt = 0; kt < 14; kt++){
            const float *p0, *p1;
            if (kt < 6)      { int ko = kt*16;        p0 = src0 + ko; p1 = src1 + ko; }
            else if (kt < 12){ int ko = kt*16 - 96;   p0 = dst0 + ko; p1 = dst1 + ko; }
            else             { int ko = kt*16 - 192;  p0 = ef0  + ko; p1 = ef1  + ko; }
            float2 f0 = *(const float2*)(p0 + kk);
            float2 f1 = *(const float2*)(p1 + kk);
            float2 f2 = *(const float2*)(p0 + kk + 8);
            float2 f3 = *(const float2*)(p1 + kk + 8);
            uint32_t Ah[4], Al[4];
            bf16_split2(f0.x, f0.y, Ah[0], Al[0]);
            bf16_split2(f1.x, f1.y, Ah[1], Al[1]);
            bf16_split2(f2.x, f2.y, Ah[2], Al[2]);
            bf16_split2(f3.x, f3.y, Ah[3], Al[3]);

            #pragma unroll
            for (int g = 0; g < 6; g++){
                uint32_t Bh[4], Bl[4];
                ldsm4(Bh, wh_base + (uint32_t)(g*16*XRB) + kt*32);
                ldsm4(Bl, wl_base + (uint32_t)(g*16*XRB) + kt*32);
                mma16816(d[2*g],   Ah, Bh);     mma16816(d[2*g],   Al, Bh);     mma16816(d[2*g],   Ah, Bl);
                mma16816(d[2*g+1], Ah, Bh+2);   mma16816(d[2*g+1], Al, Bh+2);   mma16816(d[2*g+1], Ah, Bl+2);
            }
        }

        #pragma unroll
        for (int j = 0; j < 2; j++){
            int eid = j ? e1 : e0;
            int dstI = j ? ((b1<<10) + ep1.y) : ((b0<<10) + ep0.y);
            int c0 = kk;

            float g[24];
            float s = 0.0f;
            #pragma unroll
            for (int nt = 0; nt < 12; nt++){
                int c = nt*8 + c0;
                float v0 = gelu_erf(d[nt][2*j]   + biasS[c]);
                float v1 = gelu_erf(d[nt][2*j+1] + biasS[c+1]);
                g[2*nt] = v0; g[2*nt+1] = v1;
                s += v0 + v1;
            }
            s += __shfl_xor_sync(0xffffffffu, s, 1);
            s += __shfl_xor_sync(0xffffffffu, s, 2);
            float mu = s * (1.0f/96.0f);
            float ssq = 0.0f;
            #pragma unroll
            for (int i = 0; i < 24; i++){ float dv = g[i]-mu; ssq += dv*dv; }
            ssq += __shfl_xor_sync(0xffffffffu, ssq, 1);
            ssq += __shfl_xor_sync(0xffffffffu, ssq, 2);
            float r = rsqrtf(ssq * (1.0f/96.0f) + LN_EPS);

            float w  = ew[eid];
            float dr = ed[2*eid+1];
            float* ow = out_wm + (size_t)eid*FF;
            float* ap = g_agg + (size_t)dstI*FF;
            #pragma unroll
            for (int nt = 0; nt < 12; nt++){
                int c = nt*8 + c0;
                float y0 = ((g[2*nt]  -mu)*r*gmS[c]   + beS[c])   * w;
                float y1 = ((g[2*nt+1]-mu)*r*gmS[c+1] + beS[c+1]) * w;
                *(float2*)(ow + c) = make_float2(y0, y1);
                atomicAdd(ap + c,     y0*dr);
                atomicAdd(ap + c + 1, y1*dr);
            }
        }
    }
}

// ---------------- q/k/v/gate projections (R6 staged version, unchanged) ----------------
__global__ __launch_bounds__(32*WPB,1)
void qkvg_kernel(const float* __restrict__ nodes,
    const float* __restrict__ Wq, const float* __restrict__ bq,
    const float* __restrict__ Wk, const float* __restrict__ bk,
    const float* __restrict__ Wv, const float* __restrict__ bv,
    const float* __restrict__ Wg, const float* __restrict__ bg){
    extern __shared__ float smemf[];
    float* sA  = smemf;
    float* sbA = sA + FF*K2P;
    float* sx  = sbA + FF;
    int m = blockIdx.y;
    const float* WA = (m==0)?Wq:((m==1)?Wk:((m==2)?Wv:Wg));
    const float* bA = (m==0)?bq:((m==1)?bk:((m==2)?bv:bg));
    float* outA     = (m==0)?g_q:((m==1)?g_k:((m==2)?g_v:g_gate));
    bool isGate = (m == 3);

    int tid = threadIdx.x;
    for (int i = tid; i < K2*FF; i += blockDim.x){
        int k = i / FF, c = i % FF;
        sA[c*K2P + k] = WA[i];
    }
    if (tid < FF) sbA[tid] = bA[tid];
    __syncthreads();

    int warp = tid>>5, lane = tid&31;
    float* x = sx + warp*(EPB*K2);
    int warpGlobal = blockIdx.x*WPB + warp;

    const ulonglong2* wp0 = (const ulonglong2*)(sA + (size_t)lane*K2P);
    const ulonglong2* wp1 = (const ulonglong2*)(sA + (size_t)(lane+32)*K2P);
    const ulonglong2* wp2 = (const ulonglong2*)(sA + (size_t)(lane+64)*K2P);

    for (int base = warpGlobal*EPB; base < BB*NN; base += gridDim.x*WPB*EPB){
        #pragma unroll
        for (int e = 0; e < EPB; e++){
            int idx = base + e;
            const float4* np = (const float4*)(nodes + (size_t)idx*FF);
            const float4* ap = (const float4*)(g_agg + (size_t)idx*FF);
            float4* xe = (float4*)(x + e*K2);
            #pragma unroll
            for (int i0 = 0; i0 < 2; i0++){
                int i = lane + 32*i0;
                if (i < 48){
                    float4 v = (i < 24) ? np[i] : ap[i-24];
                    xe[i] = v;
                }
            }
        }
        __syncwarp();

        u64 a0[EPB], a1[EPB], a2[EPB];
        #pragma unroll
        for (int e = 0; e < EPB; e++){ a0[e]=0ull; a1[e]=0ull; a2[e]=0ull; }

        #pragma unroll 4
        for (int ks = 0; ks < K2/4; ks++){
            ulonglong2 w0 = wp0[ks], w1 = wp1[ks], w2 = wp2[ks];
            #pragma unroll
            for (int e = 0; e < EPB; e++){
                ulonglong2 xv = ((const ulonglong2*)(x + e*K2))[ks];
                a0[e] = ffma2(xv.x, w0.x, a0[e]); a0[e] = ffma2(xv.y, w0.y, a0[e]);
                a1[e] = ffma2(xv.x, w1.x, a1[e]); a1[e] = ffma2(xv.y, w1.y, a1[e]);
                a2[e] = ffma2(xv.x, w2.x, a2[e]); a2[e] = ffma2(xv.y, w2.y, a2[e]);
            }
        }
        __syncwarp();

        #pragma unroll
        for (int e = 0; e < EPB; e++){
            int idx = base + e;
            int b = idx >> 10, n = idx & (NN-1);
            float vals[3];
            vals[0] = psum2(a0[e]) + sbA[lane];
            vals[1] = psum2(a1[e]) + sbA[lane+32];
            vals[2] = psum2(a2[e]) + sbA[lane+64];
            #pragma unroll
            for (int c = 0; c < 3; c++){
                int col = lane + 32*c;
                int h = col >> 3, dl = col & 7;
                size_t off = ((size_t)(b*HH + h)*NN + n)*DD + dl;
                float v = vals[c];
                if (isGate) v = 1.0f/(1.0f + __expf(-v));
                outA[off] = v;
            }
        }
        __syncwarp();
    }
}

// ================= attention: warp-mma flash, hi/lo bf16 =================
// smem: KH@0 [1024][8]bf16 (16KB), KL@16384, VTH@32768 [8][1032]bf16 (16512B), VTL@49280
#define A_OKH 0
#define A_OKL 16384
#define A_OVH 32768
#define A_OVL 49280
#define A_VSTRIDE 2064
#define ATTN_SMEM 66048
#define KSB 64

__global__ __launch_bounds__(256,2)
void attn_mma_kernel(){
    extern __shared__ char smem[];
    uint32_t sb = smem_u32(smem);
    int bh = blockIdx.x;
    int b = bh / HH, h = bh % HH;
    int tid = threadIdx.x, wid = tid >> 5, lane = tid & 31;

    // stage K hi/lo [key][8] and V^T hi/lo [8][1032]
    for (int j = tid; j < NN; j += 256){
        const float4* kp = (const float4*)(g_k + ((size_t)bh*NN + j)*DD);
        float4 k0 = kp[0], k1 = kp[1];
        uint32_t h0,h1,h2,h3,l0,l1,l2,l3;
        bf16_split2(k0.x,k0.y,h0,l0); bf16_split2(k0.z,k0.w,h1,l1);
        bf16_split2(k1.x,k1.y,h2,l2); bf16_split2(k1.z,k1.w,h3,l3);
        *(uint4*)(smem + A_OKH + j*16) = make_uint4(h0,h1,h2,h3);
        *(uint4*)(smem + A_OKL + j*16) = make_uint4(l0,l1,l2,l3);

        const float4* vp = (const float4*)(g_v + ((size_t)bh*NN + j)*DD);
        float4 v0 = vp[0], v1 = vp[1];
        float vv[8] = {v0.x,v0.y,v0.z,v0.w,v1.x,v1.y,v1.z,v1.w};
        #pragma unroll
        for (int d = 0; d < 8; d++){
            __nv_bfloat16 hb = __float2bfloat16_rn(vv[d]);
            float hf = __bfloat162float(hb);
            __nv_bfloat16 lb = __float2bfloat16_rn(vv[d] - hf);
            *(__nv_bfloat16*)(smem + A_OVH + d*A_VSTRIDE + j*2) = hb;
            *(__nv_bfloat16*)(smem + A_OVL + d*A_VSTRIDE + j*2) = lb;
        }
    }
    __syncthreads();

    // Q fragments (pre-scaled, hi/lo)
    int r0 = blockIdx.y*128 + wid*16 + (lane >> 2);
    int r1 = r0 + 8;
    int c0 = 2*(lane & 3);
    float2 q0 = *(const float2*)(g_q + ((size_t)bh*NN + r0)*DD + c0);
    float2 q1 = *(const float2*)(g_q + ((size_t)bh*NN + r1)*DD + c0);
    uint32_t Ah[2], Al[2];
    bf16_split2(q0.x*ATT_SCALE, q0.y*ATT_SCALE, Ah[0], Al[0]);
    bf16_split2(q1.x*ATT_SCALE, q1.y*ATT_SCALE, Ah[1], Al[1]);

    float m0 = -3.4e38f, m1 = -3.4e38f, la0 = 0.0f, la1 = 0.0f;
    float O[4] = {0.0f, 0.0f, 0.0f, 0.0f};

    uint32_t vBase = (lane & 7)*A_VSTRIDE + ((lane >> 3) & 3)*16;

    #pragma unroll 1
    for (int kb = 0; kb < NN/KSB; kb++){
        uint32_t kh[8], kl[8];
        ldsm4(kh,     sb + A_OKH + (kb*KSB + lane)*16);
        ldsm4(kh + 4, sb + A_OKH + (kb*KSB + 32 + lane)*16);
        ldsm4(kl,     sb + A_OKL + (kb*KSB + lane)*16);
        ldsm4(kl + 4, sb + A_OKL + (kb*KSB + 32 + lane)*16);

        float s[8][4];
        #pragma unroll
        for (int nt = 0; nt < 8; nt++){ s[nt][0]=s[nt][1]=s[nt][2]=s[nt][3]=0.0f; }
        #pragma unroll
        for (int nt = 0; nt < 8; nt++){
            mma1688(s[nt], Ah, kh[nt]);
            mma1688(s[nt], Al, kh[nt]);
            mma1688(s[nt], Ah, kl[nt]);
        }

        float bm0 = s[0][0], bm1 = s[0][2];
        #pragma unroll
        for (int nt = 0; nt < 8; nt++){
            bm0 = fmaxf(bm0, fmaxf(s[nt][0], s[nt][1]));
            bm1 = fmaxf(bm1, fmaxf(s[nt][2], s[nt][3]));
        }
        bm0 = fmaxf(bm0, __shfl_xor_sync(0xffffffffu, bm0, 1));
        bm0 = fmaxf(bm0, __shfl_xor_sync(0xffffffffu, bm0, 2));
        bm1 = fmaxf(bm1, __shfl_xor_sync(0xffffffffu, bm1, 1));
        bm1 = fmaxf(bm1, __shfl_xor_sync(0xffffffffu, bm1, 2));
        float mn0 = fmaxf(m0, bm0), mn1 = fmaxf(m1, bm1);
        float fac0 = __expf(m0 - mn0), fac1 = __expf(m1 - mn1);
        m0 = mn0; m1 = mn1;
        O[0] *= fac0; O[1] *= fac0; O[2] *= fac1; O[3] *= fac1;

        uint32_t vh[8], vl[8];
        uint32_t vaddr = sb + vBase + kb*KSB*2;
        ldsm4(vh,     A_OVH + vaddr);
        ldsm4(vh + 4, A_OVH + vaddr + 64);
        ldsm4(vl,     A_OVL + vaddr);
        ldsm4(vl + 4, A_OVL + vaddr + 64);

        float rs0 = 0.0f, rs1 = 0.0f;
        #pragma unroll
        for (int kt = 0; kt < 4; kt++){
            float p0 = __expf(s[2*kt][0]   - mn0);
            float p1 = __expf(s[2*kt][1]   - mn0);
            float p2 = __expf(s[2*kt][2]   - mn1);
            float p3 = __expf(s[2*kt][3]   - mn1);
            float p4 = __expf(s[2*kt+1][0] - mn0);
            float p5 = __expf(s[2*kt+1][1] - mn0);
            float p6 = __expf(s[2*kt+1][2] - mn1);
            float p7 = __expf(s[2*kt+1][3] - mn1);
            rs0 += (p0 + p1) + (p4 + p5);
            rs1 += (p2 + p3) + (p6 + p7);
            uint32_t Ph[4], Pl[4];
            bf16_split2(p0, p1, Ph[0], Pl[0]);
            bf16_split2(p2, p3, Ph[1], Pl[1]);
            bf16_split2(p4, p5, Ph[2], Pl[2]);
            bf16_split2(p6, p7, Ph[3], Pl[3]);
            mma16816(O, Ph, vh + kt*2);
            mma16816(O, Pl, vh + kt*2);
            mma16816(O, Ph, vl + kt*2);
        }
        rs0 += __shfl_xor_sync(0xffffffffu, rs0, 1);
        rs0 += __shfl_xor_sync(0xffffffffu, rs0, 2);
        rs1 += __shfl_xor_sync(0xffffffffu, rs1, 1);
        rs1 += __shfl_xor_sync(0xffffffffu, rs1, 2);
        la0 = la0*fac0 + rs0;
        la1 = la1*fac1 + rs1;
    }

    float inv0 = 1.0f / la0, inv1 = 1.0f / la1;
    float2 g0 = *(const float2*)(g_gate + ((size_t)bh*NN + r0)*DD + c0);
    float2 g1 = *(const float2*)(g_gate + ((size_t)bh*NN + r1)*DD + c0);
    *(float2*)(g_att + ((size_t)((b<<10) + r0))*FF + h*DD + c0) =
        make_float2(O[0]*inv0*g0.x, O[1]*inv0*g0.y);
    *(float2*)(g_att + ((size_t)((b<<10) + r1))*FF + h*DD + c0) =
        make_float2(O[2]*inv1*g1.x, O[3]*inv1*g1.y);
}

// ---------------- output: LN(GELU(att @ Wo + bo)) ----------------
__global__ __launch_bounds__(512,1)
void out_kernel(const float* __restrict__ Wo, const float* __restrict__ bo,
                const float* __restrict__ gu, const float* __restrict__ betau,
                float* __restrict__ out){
    __shared__ float sW[FF*FF];
    __shared__ float sb[FF], sg[FF], sbe[FF];
    __shared__ float sx[16*FF];
    int tid = threadIdx.x;
    for (int i = tid; i < FF*FF; i += blockDim.x) sW[i] = Wo[i];
    if (tid < FF){ sb[tid]=bo[tid]; sg[tid]=gu[tid]; sbe[tid]=betau[tid]; }
    __syncthreads();

    int warp = tid>>5, lane = tid&31;
    float* x = sx + warp*FF;
    for (int idx = blockIdx.x*16 + warp; idx < BB*NN; idx += gridDim.x*16){
        const float* ap = g_att + (size_t)idx*FF;
        for (int i = lane; i < FF; i += 32) x[i] = ap[i];
        __syncwarp();
        float a0 = sb[lane], a1 = sb[lane+32], a2 = sb[lane+64];
        #pragma unroll 4
        for (int k = 0; k < FF; k++){
            float xv = x[k];
            a0 = fmaf(xv, sW[k*FF+lane],    a0);
            a1 = fmaf(xv, sW[k*FF+lane+32], a1);
            a2 = fmaf(xv, sW[k*FF+lane+64], a2);
        }
        a0 = gelu_erf(a0); a1 = gelu_erf(a1); a2 = gelu_erf(a2);
        float s = a0 + a1 + a2;
        #pragma unroll
        for (int off = 16; off; off >>= 1) s += __shfl_xor_sync(0xffffffffu, s, off);
        float mu = s * (1.0f/96.0f);
        float d0 = a0-mu, d1 = a1-mu, d2 = a2-mu;
        float ssq = d0*d0 + d1*d1 + d2*d2;
        #pragma unroll
        for (int off = 16; off; off >>= 1) ssq += __shfl_xor_sync(0xffffffffu, ssq, off);
        float r = rsqrtf(ssq * (1.0f/96.0f) + LN_EPS);
        float* op = out + (size_t)idx*FF;
        op[lane]    = d0*r*sg[lane]    + sbe[lane];
        op[lane+32] = d1*r*sg[lane+32] + sbe[lane+32];
        op[lane+64] = d2*r*sg[lane+64] + sbe[lane+64];
        __syncwarp();
    }
}

// ---------------- launch ----------------
extern "C" void kernel_launch(void* const* d_in, const int* in_sizes, int n_in,
                              void* d_out, int out_size){
    const float* nodes = (const float*)d_in[0];
    const float* efeat = (const float*)d_in[1];
    const int*   edges = (const int*)  d_in[2];
    const float* ew    = (const float*)d_in[3];
    const float* ed    = (const float*)d_in[4];
    const float* Wm    = (const float*)d_in[5];
    const float* bm    = (const float*)d_in[6];
    const float* gm    = (const float*)d_in[7];
    const float* betam = (const float*)d_in[8];
    const float* Wq=(const float*)d_in[9],  *bq=(const float*)d_in[10];
    const float* Wk=(const float*)d_in[11], *bk=(const float*)d_in[12];
    const float* Wv=(const float*)d_in[13], *bv=(const float*)d_in[14];
    const float* Wg=(const float*)d_in[15], *bg=(const float*)d_in[16];
    const float* Wo=(const float*)d_in[17], *bo=(const float*)d_in[18];
    const float* gu=(const float*)d_in[19], *betau=(const float*)d_in[20];
    float* out = (float*)d_out;

    const size_t OFF_WM    = (size_t)BB*NN*FF;
    const size_t OFF_EDGES = OFF_WM + (size_t)BB*EE*FF;
    const size_t OFF_EW    = OFF_EDGES + (size_t)BB*EE*2;
    const size_t OFF_ED    = OFF_EW + (size_t)BB*EE;

    const int QKVG_SMEM = (FF*K2P + FF + WPB*EPB*K2)*4;     // 173952 B
    cudaFuncSetAttribute(msg_mma_kernel,  cudaFuncAttributeMaxDynamicSharedMemorySize, MSG_SMEM);
    cudaFuncSetAttribute(qkvg_kernel,     cudaFuncAttributeMaxDynamicSharedMemorySize, QKVG_SMEM);
    cudaFuncSetAttribute(attn_mma_kernel, cudaFuncAttributeMaxDynamicSharedMemorySize, ATTN_SMEM);

    zero_agg_kernel<<<(BB*NN*FF+255)/256, 256>>>();
    passthrough_kernel<<<(BB*EE*2+255)/256, 256>>>(edges, ew, ed,
                                                   out+OFF_EDGES, out+OFF_EW, out+OFF_ED);
    msg_mma_kernel<<<296, 256, MSG_SMEM>>>(nodes, efeat, edges, ew, ed,
                                           Wm, bm, gm, betam, out+OFF_WM);
    qkvg_kernel<<<dim3(37,4), 32*WPB, QKVG_SMEM>>>(nodes, Wq,bq, Wk,bk, Wv,bv, Wg,bg);
    attn_mma_kernel<<<dim3(BB*HH,8), 256, ATTN_SMEM>>>();
    out_kernel<<<148, 512>>>(Wo, bo, gu, betau, out);
}

// round 13
// speedup vs baseline: 2.2714x; 1.0734x over previous
#include <cuda_runtime.h>
#include <cuda_bf16.h>
#include <math.h>
#include <stdint.h>

#define BB 8
#define NN 1024
#define EE 16384
#define FF 96
#define FE 32
#define HH 12
#define DD 8
#define KM 224
#define K2 192
#define LN_EPS 1e-3f
#define ATT_SCALE 0.35355339059327373f

typedef unsigned long long u64;

__device__ __forceinline__ float gelu_erf(float x){
    return 0.5f * x * (1.0f + erff(x * 0.70710678118654752f));
}

// ---------------- warp-mma helpers ----------------
__device__ __forceinline__ uint32_t smem_u32(const void* p){
    uint32_t a;
    asm("{ .reg .u64 t; cvta.to.shared.u64 t, %1; cvt.u32.u64 %0, t; }" : "=r"(a) : "l"(p));
    return a;
}
__device__ __forceinline__ void ldsm4(uint32_t* r, uint32_t addr){
    asm volatile("ldmatrix.sync.aligned.m8n8.x4.shared.b16 {%0,%1,%2,%3}, [%4];"
        : "=r"(r[0]), "=r"(r[1]), "=r"(r[2]), "=r"(r[3]) : "r"(addr));
}
__device__ __forceinline__ void mma16816(float* d, const uint32_t* a, const uint32_t* b){
    asm volatile("mma.sync.aligned.m16n8k16.row.col.f32.bf16.bf16.f32 "
        "{%0,%1,%2,%3}, {%4,%5,%6,%7}, {%8,%9}, {%0,%1,%2,%3};"
        : "+f"(d[0]), "+f"(d[1]), "+f"(d[2]), "+f"(d[3])
        : "r"(a[0]), "r"(a[1]), "r"(a[2]), "r"(a[3]), "r"(b[0]), "r"(b[1]));
}
__device__ __forceinline__ void mma1688(float* d, const uint32_t* a, uint32_t b){
    asm volatile("mma.sync.aligned.m16n8k8.row.col.f32.bf16.bf16.f32 "
        "{%0,%1,%2,%3}, {%4,%5}, {%6}, {%0,%1,%2,%3};"
        : "+f"(d[0]), "+f"(d[1]), "+f"(d[2]), "+f"(d[3])
        : "r"(a[0]), "r"(a[1]), "r"(b));
}
__device__ __forceinline__ void bf16_split2(float x0, float x1, uint32_t &h, uint32_t &l){
    asm("cvt.rn.bf16x2.f32 %0, %1, %2;" : "=r"(h) : "f"(x1), "f"(x0));
    float h0 = __uint_as_float(h << 16);
    float h1 = __uint_as_float(h & 0xffff0000u);
    float r0 = x0 - h0, r1 = x1 - h1;
    asm("cvt.rn.bf16x2.f32 %0, %1, %2;" : "=r"(l) : "f"(r1), "f"(r0));
}

// ---------------- scratch ----------------
__device__ float g_agg [BB*NN*FF];
__device__ float g_q   [BB*HH*NN*DD];
__device__ float g_k   [BB*HH*NN*DD];
__device__ float g_v   [BB*HH*NN*DD];
__device__ float g_gate[BB*HH*NN*DD];
__device__ float g_att [BB*NN*FF];

// ---------------- helpers ----------------
__global__ void zero_agg_kernel(){
    int i = blockIdx.x*blockDim.x + threadIdx.x;
    if (i < BB*NN*FF) g_agg[i] = 0.0f;
}

__global__ void passthrough_kernel(const int* __restrict__ edges,
                                   const float* __restrict__ ew,
                                   const float* __restrict__ ed,
                                   float* __restrict__ out_edges,
                                   float* __restrict__ out_ew,
                                   float* __restrict__ out_ed){
    int i = blockIdx.x*blockDim.x + threadIdx.x;
    if (i < BB*EE*2){ out_edges[i] = (float)edges[i]; out_ed[i] = ed[i]; }
    if (i < BB*EE)  out_ew[i] = ew[i];
}

// ================= message kernel (R10 winner, unchanged) =================
#define XST 232
#define XRB (XST*2)
#define OFF_BIAS 1024
#define OFF_GM   1408
#define OFF_BE   1792
#define OFF_WH   2304
#define OFF_WL   (OFF_WH + 96*XRB)
#define MSG_SMEM (OFF_WL + 96*XRB)
#define NSTRIPS (BB*EE/16)

__global__ __launch_bounds__(256,2)
void msg_mma_kernel(const float* __restrict__ nodes, const float* __restrict__ efeat,
                    const int* __restrict__ edges, const float* __restrict__ ew,
                    const float* __restrict__ ed, const float* __restrict__ Wm,
                    const float* __restrict__ bm, const float* __restrict__ gm,
                    const float* __restrict__ betam, float* __restrict__ out_wm){
    extern __shared__ char smem[];
    uint32_t sb = smem_u32(smem);
    int tid = threadIdx.x, wid = tid >> 5, lane = tid & 31;

    float* biasS = (float*)(smem + OFF_BIAS);
    float* gmS   = (float*)(smem + OFF_GM);
    float* beS   = (float*)(smem + OFF_BE);

    for (int idx = tid; idx < KM*FF; idx += 256){
        int k = idx / FF, n = idx % FF;
        float w = Wm[idx];
        __nv_bfloat16 hb = __float2bfloat16_rn(w);
        float hf = __bfloat162float(hb);
        __nv_bfloat16 lb = __float2bfloat16_rn(w - hf);
        *(__nv_bfloat16*)(smem + OFF_WH + n*XRB + k*2) = hb;
        *(__nv_bfloat16*)(smem + OFF_WL + n*XRB + k*2) = lb;
    }
    if (tid < FF){ biasS[tid] = bm[tid]; gmS[tid] = gm[tid]; beS[tid] = betam[tid]; }
    __syncthreads();

    uint32_t bRow = (uint32_t)((lane & 7) + ((lane >> 4) & 1)*8);
    uint32_t bOff = bRow*XRB + (((lane >> 3) & 1) * 16);
    uint32_t wh_base = sb + OFF_WH + bOff;
    uint32_t wl_base = sb + OFF_WL + bOff;

    int kk = 2*(lane & 3);

    for (int strip = blockIdx.x*8 + wid; strip < NSTRIPS; strip += gridDim.x*8){
        int e0 = strip*16 + (lane >> 2);
        int e1 = e0 + 8;
        int2 ep0 = *(const int2*)(edges + 2*e0);
        int2 ep1 = *(const int2*)(edges + 2*e1);
        int b0 = e0 >> 14, b1 = e1 >> 14;
        const float* src0 = nodes + (size_t)((b0<<10) + ep0.x)*FF;
        const float* dst0 = nodes + (size_t)((b0<<10) + ep0.y)*FF;
        const float* src1 = nodes + (size_t)((b1<<10) + ep1.x)*FF;
        const float* dst1 = nodes + (size_t)((b1<<10) + ep1.y)*FF;
        const float* ef0  = efeat + (size_t)e0*FE;
        const float* ef1  = efeat + (size_t)e1*FE;

        float d[12][4];
        #pragma unroll
        for (int nt = 0; nt < 12; nt++){ d[nt][0]=d[nt][1]=d[nt][2]=d[nt][3]=0.0f; }

        #pragma unroll 1
        for (int kt = 0; kt < 14; kt++){
            const float *p0, *p1;
            if (kt < 6)      { int ko = kt*16;        p0 = src0 + ko; p1 = src1 + ko; }
            else if (kt < 12){ int ko = kt*16 - 96;   p0 = dst0 + ko; p1 = dst1 + ko; }
            else             { int ko = kt*16 - 192;  p0 = ef0  + ko; p1 = ef1  + ko; }
            float2 f0 = *(const float2*)(p0 + kk);
            float2 f1 = *(const float2*)(p1 + kk);
            float2 f2 = *(const float2*)(p0 + kk + 8);
            float2 f3 = *(const float2*)(p1 + kk + 8);
            uint32_t Ah[4], Al[4];
            bf16_split2(f0.x, f0.y, Ah[0], Al[0]);
            bf16_split2(f1.x, f1.y, Ah[1], Al[1]);
            bf16_split2(f2.x, f2.y, Ah[2], Al[2]);
            bf16_split2(f3.x, f3.y, Ah[3], Al[3]);

            #pragma unroll
            for (int g = 0; g < 6; g++){
                uint32_t Bh[4], Bl[4];
                ldsm4(Bh, wh_base + (uint32_t)(g*16*XRB) + kt*32);
                ldsm4(Bl, wl_base + (uint32_t)(g*16*XRB) + kt*32);
                mma16816(d[2*g],   Ah, Bh);     mma16816(d[2*g],   Al, Bh);     mma16816(d[2*g],   Ah, Bl);
                mma16816(d[2*g+1], Ah, Bh+2);   mma16816(d[2*g+1], Al, Bh+2);   mma16816(d[2*g+1], Ah, Bl+2);
            }
        }

        #pragma unroll
        for (int j = 0; j < 2; j++){
            int eid = j ? e1 : e0;
            int dstI = j ? ((b1<<10) + ep1.y) : ((b0<<10) + ep0.y);
            int c0 = kk;

            float g[24];
            float s = 0.0f;
            #pragma unroll
            for (int nt = 0; nt < 12; nt++){
                int c = nt*8 + c0;
                float v0 = gelu_erf(d[nt][2*j]   + biasS[c]);
                float v1 = gelu_erf(d[nt][2*j+1] + biasS[c+1]);
                g[2*nt] = v0; g[2*nt+1] = v1;
                s += v0 + v1;
            }
            s += __shfl_xor_sync(0xffffffffu, s, 1);
            s += __shfl_xor_sync(0xffffffffu, s, 2);
            float mu = s * (1.0f/96.0f);
            float ssq = 0.0f;
            #pragma unroll
            for (int i = 0; i < 24; i++){ float dv = g[i]-mu; ssq += dv*dv; }
            ssq += __shfl_xor_sync(0xffffffffu, ssq, 1);
            ssq += __shfl_xor_sync(0xffffffffu, ssq, 2);
            float r = rsqrtf(ssq * (1.0f/96.0f) + LN_EPS);

            float w  = ew[eid];
            float dr = ed[2*eid+1];
            float* ow = out_wm + (size_t)eid*FF;
            float* ap = g_agg + (size_t)dstI*FF;
            #pragma unroll
            for (int nt = 0; nt < 12; nt++){
                int c = nt*8 + c0;
                float y0 = ((g[2*nt]  -mu)*r*gmS[c]   + beS[c])   * w;
                float y1 = ((g[2*nt+1]-mu)*r*gmS[c+1] + beS[c+1]) * w;
                *(float2*)(ow + c) = make_float2(y0, y1);
                atomicAdd(ap + c,     y0*dr);
                atomicAdd(ap + c + 1, y1*dr);
            }
        }
    }
}

// ================= qkvg: warp-mma, direct-from-global A =================
// smem per matrix: bias@0 [96]f, WH@512 [96][200]bf16 (38400B), WL@38912 ; total 77312
#define QST 200
#define QRB (QST*2)          // 400 B row stride (mod 128 = 16 -> conflict-free groups)
#define Q_BIAS 0
#define Q_WH   512
#define Q_WL   (Q_WH + 96*QRB)
#define QKVG_SMEM (Q_WL + 96*QRB)

__global__ __launch_bounds__(256,2)
void qkvg_mma_kernel(const float* __restrict__ nodes,
    const float* __restrict__ Wq, const float* __restrict__ bq,
    const float* __restrict__ Wk, const float* __restrict__ bk,
    const float* __restrict__ Wv, const float* __restrict__ bv,
    const float* __restrict__ Wg, const float* __restrict__ bg){
    extern __shared__ char smem[];
    uint32_t sb = smem_u32(smem);
    int tid = threadIdx.x, wid = tid >> 5, lane = tid & 31;
    int m = blockIdx.y;
    const float* WA = (m==0)?Wq:((m==1)?Wk:((m==2)?Wv:Wg));
    const float* bA = (m==0)?bq:((m==1)?bk:((m==2)?bv:bg));
    float* outA     = (m==0)?g_q:((m==1)?g_k:((m==2)?g_v:g_gate));
    bool isGate = (m == 3);

    float* biasS = (float*)(smem + Q_BIAS);

    for (int idx = tid; idx < K2*FF; idx += 256){
        int k = idx / FF, n = idx % FF;
        float w = WA[idx];
        __nv_bfloat16 hb = __float2bfloat16_rn(w);
        float hf = __bfloat162float(hb);
        __nv_bfloat16 lb = __float2bfloat16_rn(w - hf);
        *(__nv_bfloat16*)(smem + Q_WH + n*QRB + k*2) = hb;
        *(__nv_bfloat16*)(smem + Q_WL + n*QRB + k*2) = lb;
    }
    if (tid < FF) biasS[tid] = bA[tid];
    __syncthreads();

    uint32_t bRow = (uint32_t)((lane & 7) + ((lane >> 4) & 1)*8);
    uint32_t bOff = bRow*QRB + (((lane >> 3) & 1) * 16);
    uint32_t wh_base = sb + Q_WH + bOff;
    uint32_t wl_base = sb + Q_WL + bOff;

    int kk = 2*(lane & 3);

    // one strip of 16 node-rows per warp: 512 strips = grid.x(64) * 8 warps
    int strip = blockIdx.x*8 + wid;
    int r0 = strip*16 + (lane >> 2);
    int r1 = r0 + 8;
    const float* n0 = nodes + (size_t)r0*FF;
    const float* n1 = nodes + (size_t)r1*FF;
    const float* a0p = g_agg + (size_t)r0*FF;
    const float* a1p = g_agg + (size_t)r1*FF;

    float d[12][4];
    #pragma unroll
    for (int nt = 0; nt < 12; nt++){ d[nt][0]=d[nt][1]=d[nt][2]=d[nt][3]=0.0f; }

    #pragma unroll 1
    for (int kt = 0; kt < 12; kt++){
        const float *p0, *p1;
        if (kt < 6){ int ko = kt*16;      p0 = n0  + ko; p1 = n1  + ko; }
        else       { int ko = kt*16 - 96; p0 = a0p + ko; p1 = a1p + ko; }
        float2 f0 = *(const float2*)(p0 + kk);
        float2 f1 = *(const float2*)(p1 + kk);
        float2 f2 = *(const float2*)(p0 + kk + 8);
        float2 f3 = *(const float2*)(p1 + kk + 8);
        uint32_t Ah[4], Al[4];
        bf16_split2(f0.x, f0.y, Ah[0], Al[0]);
        bf16_split2(f1.x, f1.y, Ah[1], Al[1]);
        bf16_split2(f2.x, f2.y, Ah[2], Al[2]);
        bf16_split2(f3.x, f3.y, Ah[3], Al[3]);

        #pragma unroll
        for (int g = 0; g < 6; g++){
            uint32_t Bh[4], Bl[4];
            ldsm4(Bh, wh_base + (uint32_t)(g*16*QRB) + kt*32);
            ldsm4(Bl, wl_base + (uint32_t)(g*16*QRB) + kt*32);
            mma16816(d[2*g],   Ah, Bh);     mma16816(d[2*g],   Al, Bh);     mma16816(d[2*g],   Ah, Bl);
            mma16816(d[2*g+1], Ah, Bh+2);   mma16816(d[2*g+1], Al, Bh+2);   mma16816(d[2*g+1], Ah, Bl+2);
        }
    }

    // epilogue: head layout store, col = nt*8 + kk -> h = nt, dl = kk
    #pragma unroll
    for (int j = 0; j < 2; j++){
        int row = j ? r1 : r0;
        int b = row >> 10, n = row & (NN-1);
        #pragma unroll
        for (int nt = 0; nt < 12; nt++){
            float v0 = d[nt][2*j]   + biasS[nt*8 + kk];
            float v1 = d[nt][2*j+1] + biasS[nt*8 + kk + 1];
            if (isGate){
                v0 = 1.0f/(1.0f + __expf(-v0));
                v1 = 1.0f/(1.0f + __expf(-v1));
            }
            size_t off = ((size_t)(b*HH + nt)*NN + n)*DD + kk;
            *(float2*)(outA + off) = make_float2(v0, v1);
        }
    }
}

// ================= attention: warp-mma flash (R12 winner, unchanged) =================
#define A_OKH 0
#define A_OKL 16384
#define A_OVH 32768
#define A_OVL 49280
#define A_VSTRIDE 2064
#define ATTN_SMEM 66048
#define KSB 64

__global__ __launch_bounds__(256,2)
void attn_mma_kernel(){
    extern __shared__ char smem[];
    uint32_t sb = smem_u32(smem);
    int bh = blockIdx.x;
    int b = bh / HH, h = bh % HH;
    int tid = threadIdx.x, wid = tid >> 5, lane = tid & 31;

    for (int j = tid; j < NN; j += 256){
        const float4* kp = (const float4*)(g_k + ((size_t)bh*NN + j)*DD);
        float4 k0 = kp[0], k1 = kp[1];
        uint32_t h0,h1,h2,h3,l0,l1,l2,l3;
        bf16_split2(k0.x,k0.y,h0,l0); bf16_split2(k0.z,k0.w,h1,l1);
        bf16_split2(k1.x,k1.y,h2,l2); bf16_split2(k1.z,k1.w,h3,l3);
        *(uint4*)(smem + A_OKH + j*16) = make_uint4(h0,h1,h2,h3);
        *(uint4*)(smem + A_OKL + j*16) = make_uint4(l0,l1,l2,l3);

        const float4* vp = (const float4*)(g_v + ((size_t)bh*NN + j)*DD);
        float4 v0 = vp[0], v1 = vp[1];
        float vv[8] = {v0.x,v0.y,v0.z,v0.w,v1.x,v1.y,v1.z,v1.w};
        #pragma unroll
        for (int d = 0; d < 8; d++){
            __nv_bfloat16 hb = __float2bfloat16_rn(vv[d]);
            float hf = __bfloat162float(hb);
            __nv_bfloat16 lb = __float2bfloat16_rn(vv[d] - hf);
            *(__nv_bfloat16*)(smem + A_OVH + d*A_VSTRIDE + j*2) = hb;
            *(__nv_bfloat16*)(smem + A_OVL + d*A_VSTRIDE + j*2) = lb;
        }
    }
    __syncthreads();

    int r0 = blockIdx.y*128 + wid*16 + (lane >> 2);
    int r1 = r0 + 8;
    int c0 = 2*(lane & 3);
    float2 q0 = *(const float2*)(g_q + ((size_t)bh*NN + r0)*DD + c0);
    float2 q1 = *(const float2*)(g_q + ((size_t)bh*NN + r1)*DD + c0);
    uint32_t Ah[2], Al[2];
    bf16_split2(q0.x*ATT_SCALE, q0.y*ATT_SCALE, Ah[0], Al[0]);
    bf16_split2(q1.x*ATT_SCALE, q1.y*ATT_SCALE, Ah[1], Al[1]);

    float m0 = -3.4e38f, m1 = -3.4e38f, la0 = 0.0f, la1 = 0.0f;
    float O[4] = {0.0f, 0.0f, 0.0f, 0.0f};

    uint32_t vBase = (lane & 7)*A_VSTRIDE + ((lane >> 3) & 3)*16;

    #pragma unroll 1
    for (int kb = 0; kb < NN/KSB; kb++){
        uint32_t kh[8], kl[8];
        ldsm4(kh,     sb + A_OKH + (kb*KSB + lane)*16);
        ldsm4(kh + 4, sb + A_OKH + (kb*KSB + 32 + lane)*16);
        ldsm4(kl,     sb + A_OKL + (kb*KSB + lane)*16);
        ldsm4(kl + 4, sb + A_OKL + (kb*KSB + 32 + lane)*16);

        float s[8][4];
        #pragma unroll
        for (int nt = 0; nt < 8; nt++){ s[nt][0]=s[nt][1]=s[nt][2]=s[nt][3]=0.0f; }
        #pragma unroll
        for (int nt = 0; nt < 8; nt++){
            mma1688(s[nt], Ah, kh[nt]);
            mma1688(s[nt], Al, kh[nt]);
            mma1688(s[nt], Ah, kl[nt]);
        }

        float bm0 = s[0][0], bm1 = s[0][2];
        #pragma unroll
        for (int nt = 0; nt < 8; nt++){
            bm0 = fmaxf(bm0, fmaxf(s[nt][0], s[nt][1]));
            bm1 = fmaxf(bm1, fmaxf(s[nt][2], s[nt][3]));
        }
        bm0 = fmaxf(bm0, __shfl_xor_sync(0xffffffffu, bm0, 1));
        bm0 = fmaxf(bm0, __shfl_xor_sync(0xffffffffu, bm0, 2));
        bm1 = fmaxf(bm1, __shfl_xor_sync(0xffffffffu, bm1, 1));
        bm1 = fmaxf(bm1, __shfl_xor_sync(0xffffffffu, bm1, 2));
        float mn0 = fmaxf(m0, bm0), mn1 = fmaxf(m1, bm1);
        float fac0 = __expf(m0 - mn0), fac1 = __expf(m1 - mn1);
        m0 = mn0; m1 = mn1;
        O[0] *= fac0; O[1] *= fac0; O[2] *= fac1; O[3] *= fac1;

        uint32_t vh[8], vl[8];
        uint32_t vaddr = sb + vBase + kb*KSB*2;
        ldsm4(vh,     A_OVH + vaddr);
        ldsm4(vh + 4, A_OVH + vaddr + 64);
        ldsm4(vl,     A_OVL + vaddr);
        ldsm4(vl + 4, A_OVL + vaddr + 64);

        float rs0 = 0.0f, rs1 = 0.0f;
        #pragma unroll
        for (int kt = 0; kt < 4; kt++){
            float p0 = __expf(s[2*kt][0]   - mn0);
            float p1 = __expf(s[2*kt][1]   - mn0);
            float p2 = __expf(s[2*kt][2]   - mn1);
            float p3 = __expf(s[2*kt][3]   - mn1);
            float p4 = __expf(s[2*kt+1][0] - mn0);
            float p5 = __expf(s[2*kt+1][1] - mn0);
            float p6 = __expf(s[2*kt+1][2] - mn1);
            float p7 = __expf(s[2*kt+1][3] - mn1);
            rs0 += (p0 + p1) + (p4 + p5);
            rs1 += (p2 + p3) + (p6 + p7);
            uint32_t Ph[4], Pl[4];
            bf16_split2(p0, p1, Ph[0], Pl[0]);
            bf16_split2(p2, p3, Ph[1], Pl[1]);
            bf16_split2(p4, p5, Ph[2], Pl[2]);
            bf16_split2(p6, p7, Ph[3], Pl[3]);
            mma16816(O, Ph, vh + kt*2);
            mma16816(O, Pl, vh + kt*2);
            mma16816(O, Ph, vl + kt*2);
        }
        rs0 += __shfl_xor_sync(0xffffffffu, rs0, 1);
        rs0 += __shfl_xor_sync(0xffffffffu, rs0, 2);
        rs1 += __shfl_xor_sync(0xffffffffu, rs1, 1);
        rs1 += __shfl_xor_sync(0xffffffffu, rs1, 2);
        la0 = la0*fac0 + rs0;
        la1 = la1*fac1 + rs1;
    }

    float inv0 = 1.0f / la0, inv1 = 1.0f / la1;
    float2 g0 = *(const float2*)(g_gate + ((size_t)bh*NN + r0)*DD + c0);
    float2 g1 = *(const float2*)(g_gate + ((size_t)bh*NN + r1)*DD + c0);
    *(float2*)(g_att + ((size_t)((b<<10) + r0))*FF + h*DD + c0) =
        make_float2(O[0]*inv0*g0.x, O[1]*inv0*g0.y);
    *(float2*)(g_att + ((size_t)((b<<10) + r1))*FF + h*DD + c0) =
        make_float2(O[2]*inv1*g1.x, O[3]*inv1*g1.y);
}

// ---------------- output: LN(GELU(att @ Wo + bo)) ----------------
__global__ __launch_bounds__(512,1)
void out_kernel(const float* __restrict__ Wo, const float* __restrict__ bo,
                const float* __restrict__ gu, const float* __restrict__ betau,
                float* __restrict__ out){
    __shared__ float sW[FF*FF];
    __shared__ float sb[FF], sg[FF], sbe[FF];
    __shared__ float sx[16*FF];
    int tid = threadIdx.x;
    for (int i = tid; i < FF*FF; i += blockDim.x) sW[i] = Wo[i];
    if (tid < FF){ sb[tid]=bo[tid]; sg[tid]=gu[tid]; sbe[tid]=betau[tid]; }
    __syncthreads();

    int warp = tid>>5, lane = tid&31;
    float* x = sx + warp*FF;
    for (int idx = blockIdx.x*16 + warp; idx < BB*NN; idx += gridDim.x*16){
        const float* ap = g_att + (size_t)idx*FF;
        for (int i = lane; i < FF; i += 32) x[i] = ap[i];
        __syncwarp();
        float a0 = sb[lane], a1 = sb[lane+32], a2 = sb[lane+64];
        #pragma unroll 4
        for (int k = 0; k < FF; k++){
            float xv = x[k];
            a0 = fmaf(xv, sW[k*FF+lane],    a0);
            a1 = fmaf(xv, sW[k*FF+lane+32], a1);
            a2 = fmaf(xv, sW[k*FF+lane+64], a2);
        }
        a0 = gelu_erf(a0); a1 = gelu_erf(a1); a2 = gelu_erf(a2);
        float s = a0 + a1 + a2;
        #pragma unroll
        for (int off = 16; off; off >>= 1) s += __shfl_xor_sync(0xffffffffu, s, off);
        float mu = s * (1.0f/96.0f);
        float d0 = a0-mu, d1 = a1-mu, d2 = a2-mu;
        float ssq = d0*d0 + d1*d1 + d2*d2;
        #pragma unroll
        for (int off = 16; off; off >>= 1) ssq += __shfl_xor_sync(0xffffffffu, ssq, off);
        float r = rsqrtf(ssq * (1.0f/96.0f) + LN_EPS);
        float* op = out + (size_t)idx*FF;
        op[lane]    = d0*r*sg[lane]    + sbe[lane];
        op[lane+32] = d1*r*sg[lane+32] + sbe[lane+32];
        op[lane+64] = d2*r*sg[lane+64] + sbe[lane+64];
        __syncwarp();
    }
}

// ---------------- launch ----------------
extern "C" void kernel_launch(void* const* d_in, const int* in_sizes, int n_in,
                              void* d_out, int out_size){
    const float* nodes = (const float*)d_in[0];
    const float* efeat = (const float*)d_in[1];
    const int*   edges = (const int*)  d_in[2];
    const float* ew    = (const float*)d_in[3];
    const float* ed    = (const float*)d_in[4];
    const float* Wm    = (const float*)d_in[5];
    const float* bm    = (const float*)d_in[6];
    const float* gm    = (const float*)d_in[7];
    const float* betam = (const float*)d_in[8];
    const float* Wq=(const float*)d_in[9],  *bq=(const float*)d_in[10];
    const float* Wk=(const float*)d_in[11], *bk=(const float*)d_in[12];
    const float* Wv=(const float*)d_in[13], *bv=(const float*)d_in[14];
    const float* Wg=(const float*)d_in[15], *bg=(const float*)d_in[16];
    const float* Wo=(const float*)d_in[17], *bo=(const float*)d_in[18];
    const float* gu=(const float*)d_in[19], *betau=(const float*)d_in[20];
    float* out = (float*)d_out;

    const size_t OFF_WM    = (size_t)BB*NN*FF;
    const size_t OFF_EDGES = OFF_WM + (size_t)BB*EE*FF;
    const size_t OFF_EW    = OFF_EDGES + (size_t)BB*EE*2;
    const size_t OFF_ED    = OFF_EW + (size_t)BB*EE;

    cudaFuncSetAttribute(msg_mma_kernel,  cudaFuncAttributeMaxDynamicSharedMemorySize, MSG_SMEM);
    cudaFuncSetAttribute(qkvg_mma_kernel, cudaFuncAttributeMaxDynamicSharedMemorySize, QKVG_SMEM);
    cudaFuncSetAttribute(attn_mma_kernel, cudaFuncAttributeMaxDynamicSharedMemorySize, ATTN_SMEM);

    zero_agg_kernel<<<(BB*NN*FF+255)/256, 256>>>();
    passthrough_kernel<<<(BB*EE*2+255)/256, 256>>>(edges, ew, ed,
                                                   out+OFF_EDGES, out+OFF_EW, out+OFF_ED);
    msg_mma_kernel<<<296, 256, MSG_SMEM>>>(nodes, efeat, edges, ew, ed,
                                           Wm, bm, gm, betam, out+OFF_WM);
    qkvg_mma_kernel<<<dim3(64,4), 256, QKVG_SMEM>>>(nodes, Wq,bq, Wk,bk, Wv,bv, Wg,bg);
    attn_mma_kernel<<<dim3(BB*HH,8), 256, ATTN_SMEM>>>();
    out_kernel<<<148, 512>>>(Wo, bo, gu, betau, out);
}

// round 16
// speedup vs baseline: 2.3657x; 1.0415x over previous
#include <cuda_runtime.h>
#include <cuda_bf16.h>
#include <math.h>
#include <stdint.h>

#define BB 8
#define NN 1024
#define EE 16384
#define FF 96
#define FE 32
#define HH 12
#define DD 8
#define KM 224
#define K2 192
#define LN_EPS 1e-3f
#define ATT_SCALE 0.35355339059327373f

typedef unsigned long long u64;

__device__ __forceinline__ float gelu_erf(float x){
    return 0.5f * x * (1.0f + erff(x * 0.70710678118654752f));
}

// ---------------- warp-mma helpers ----------------
__device__ __forceinline__ uint32_t smem_u32(const void* p){
    uint32_t a;
    asm("{ .reg .u64 t; cvta.to.shared.u64 t, %1; cvt.u32.u64 %0, t; }" : "=r"(a) : "l"(p));
    return a;
}
__device__ __forceinline__ void ldsm4(uint32_t* r, uint32_t addr){
    asm volatile("ldmatrix.sync.aligned.m8n8.x4.shared.b16 {%0,%1,%2,%3}, [%4];"
        : "=r"(r[0]), "=r"(r[1]), "=r"(r[2]), "=r"(r[3]) : "r"(addr));
}
__device__ __forceinline__ void mma16816(float* d, const uint32_t* a, const uint32_t* b){
    asm volatile("mma.sync.aligned.m16n8k16.row.col.f32.bf16.bf16.f32 "
        "{%0,%1,%2,%3}, {%4,%5,%6,%7}, {%8,%9}, {%0,%1,%2,%3};"
        : "+f"(d[0]), "+f"(d[1]), "+f"(d[2]), "+f"(d[3])
        : "r"(a[0]), "r"(a[1]), "r"(a[2]), "r"(a[3]), "r"(b[0]), "r"(b[1]));
}
__device__ __forceinline__ void mma1688(float* d, const uint32_t* a, uint32_t b){
    asm volatile("mma.sync.aligned.m16n8k8.row.col.f32.bf16.bf16.f32 "
        "{%0,%1,%2,%3}, {%4,%5}, {%6}, {%0,%1,%2,%3};"
        : "+f"(d[0]), "+f"(d[1]), "+f"(d[2]), "+f"(d[3])
        : "r"(a[0]), "r"(a[1]), "r"(b));
}
__device__ __forceinline__ void bf16_split2(float x0, float x1, uint32_t &h, uint32_t &l){
    asm("cvt.rn.bf16x2.f32 %0, %1, %2;" : "=r"(h) : "f"(x1), "f"(x0));
    float h0 = __uint_as_float(h << 16);
    float h1 = __uint_as_float(h & 0xffff0000u);
    float r0 = x0 - h0, r1 = x1 - h1;
    asm("cvt.rn.bf16x2.f32 %0, %1, %2;" : "=r"(l) : "f"(r1), "f"(r0));
}

// ---------------- scratch ----------------
__device__ float g_agg [BB*NN*FF];
__device__ float g_q   [BB*HH*NN*DD];
__device__ float g_k   [BB*HH*NN*DD];
__device__ float g_v   [BB*HH*NN*DD];
__device__ float g_gate[BB*HH*NN*DD];
__device__ float g_att [BB*NN*FF];

// ---------------- fused zero_agg + passthrough ----------------
__global__ void prep_kernel(const int* __restrict__ edges,
                            const float* __restrict__ ew,
                            const float* __restrict__ ed,
                            float* __restrict__ out_edges,
                            float* __restrict__ out_ew,
                            float* __restrict__ out_ed){
    int i = blockIdx.x*blockDim.x + threadIdx.x;
    if (i < BB*NN*FF) g_agg[i] = 0.0f;
    if (i < BB*EE*2){ out_edges[i] = (float)edges[i]; out_ed[i] = ed[i]; }
    if (i < BB*EE)  out_ew[i] = ew[i];
}

// ================= message kernel: warp-mma + prefetched A loads =================
#define XST 232
#define XRB (XST*2)
#define OFF_BIAS 1024
#define OFF_GM   1408
#define OFF_BE   1792
#define OFF_WH   2304
#define OFF_WL   (OFF_WH + 96*XRB)
#define MSG_SMEM (OFF_WL + 96*XRB)
#define NSTRIPS (BB*EE/16)

__global__ __launch_bounds__(256,2)
void msg_mma_kernel(const float* __restrict__ nodes, const float* __restrict__ efeat,
                    const int* __restrict__ edges, const float* __restrict__ ew,
                    const float* __restrict__ ed, const float* __restrict__ Wm,
                    const float* __restrict__ bm, const float* __restrict__ gm,
                    const float* __restrict__ betam, float* __restrict__ out_wm){
    extern __shared__ char smem[];
    uint32_t sb = smem_u32(smem);
    int tid = threadIdx.x, wid = tid >> 5, lane = tid & 31;

    float* biasS = (float*)(smem + OFF_BIAS);
    float* gmS   = (float*)(smem + OFF_GM);
    float* beS   = (float*)(smem + OFF_BE);

    for (int idx = tid; idx < KM*FF; idx += 256){
        int k = idx / FF, n = idx % FF;
        float w = Wm[idx];
        __nv_bfloat16 hb = __float2bfloat16_rn(w);
        float hf = __bfloat162float(hb);
        __nv_bfloat16 lb = __float2bfloat16_rn(w - hf);
        *(__nv_bfloat16*)(smem + OFF_WH + n*XRB + k*2) = hb;
        *(__nv_bfloat16*)(smem + OFF_WL + n*XRB + k*2) = lb;
    }
    if (tid < FF){ biasS[tid] = bm[tid]; gmS[tid] = gm[tid]; beS[tid] = betam[tid]; }
    __syncthreads();

    uint32_t bRow = (uint32_t)((lane & 7) + ((lane >> 4) & 1)*8);
    uint32_t bOff = bRow*XRB + (((lane >> 3) & 1) * 16);
    uint32_t wh_base = sb + OFF_WH + bOff;
    uint32_t wl_base = sb + OFF_WL + bOff;

    int kk = 2*(lane & 3);

    for (int strip = blockIdx.x*8 + wid; strip < NSTRIPS; strip += gridDim.x*8){
        int e0 = strip*16 + (lane >> 2);
        int e1 = e0 + 8;
        int2 ep0 = *(const int2*)(edges + 2*e0);
        int2 ep1 = *(const int2*)(edges + 2*e1);
        int b0 = e0 >> 14, b1 = e1 >> 14;
        const float* src0 = nodes + (size_t)((b0<<10) + ep0.x)*FF;
        const float* dst0 = nodes + (size_t)((b0<<10) + ep0.y)*FF;
        const float* src1 = nodes + (size_t)((b1<<10) + ep1.x)*FF;
        const float* dst1 = nodes + (size_t)((b1<<10) + ep1.y)*FF;
        const float* ef0  = efeat + (size_t)e0*FE;
        const float* ef1  = efeat + (size_t)e1*FE;

        float d[12][4];
        #pragma unroll
        for (int nt = 0; nt < 12; nt++){ d[nt][0]=d[nt][1]=d[nt][2]=d[nt][3]=0.0f; }

        // prologue: loads for kt=0
        float2 f0 = *(const float2*)(src0 + kk);
        float2 f1 = *(const float2*)(src1 + kk);
        float2 f2 = *(const float2*)(src0 + kk + 8);
        float2 f3 = *(const float2*)(src1 + kk + 8);

        #pragma unroll 1
        for (int kt = 0; kt < 14; kt++){
            // prefetch kt+1 A loads (cover their latency with this kt's MMA work)
            float2 n0, n1, n2, n3;
            if (kt < 13){
                int kn = kt + 1;
                const float *p0, *p1;
                if (kn < 6)      { int ko = kn*16;        p0 = src0 + ko; p1 = src1 + ko; }
                else if (kn < 12){ int ko = kn*16 - 96;   p0 = dst0 + ko; p1 = dst1 + ko; }
                else             { int ko = kn*16 - 192;  p0 = ef0  + ko; p1 = ef1  + ko; }
                n0 = *(const float2*)(p0 + kk);
                n1 = *(const float2*)(p1 + kk);
                n2 = *(const float2*)(p0 + kk + 8);
                n3 = *(const float2*)(p1 + kk + 8);
            }

            uint32_t Ah[4], Al[4];
            bf16_split2(f0.x, f0.y, Ah[0], Al[0]);
            bf16_split2(f1.x, f1.y, Ah[1], Al[1]);
            bf16_split2(f2.x, f2.y, Ah[2], Al[2]);
            bf16_split2(f3.x, f3.y, Ah[3], Al[3]);

            #pragma unroll
            for (int g = 0; g < 6; g++){
                uint32_t Bh[4], Bl[4];
                ldsm4(Bh, wh_base + (uint32_t)(g*16*XRB) + kt*32);
                ldsm4(Bl, wl_base + (uint32_t)(g*16*XRB) + kt*32);
                mma16816(d[2*g],   Ah, Bh);     mma16816(d[2*g],   Al, Bh);     mma16816(d[2*g],   Ah, Bl);
                mma16816(d[2*g+1], Ah, Bh+2);   mma16816(d[2*g+1], Al, Bh+2);   mma16816(d[2*g+1], Ah, Bl+2);
            }
            f0 = n0; f1 = n1; f2 = n2; f3 = n3;
        }

        #pragma unroll
        for (int j = 0; j < 2; j++){
            int eid = j ? e1 : e0;
            int dstI = j ? ((b1<<10) + ep1.y) : ((b0<<10) + ep0.y);
            int c0 = kk;

            float g[24];
            float s = 0.0f;
            #pragma unroll
            for (int nt = 0; nt < 12; nt++){
                int c = nt*8 + c0;
                float v0 = gelu_erf(d[nt][2*j]   + biasS[c]);
                float v1 = gelu_erf(d[nt][2*j+1] + biasS[c+1]);
                g[2*nt] = v0; g[2*nt+1] = v1;
                s += v0 + v1;
            }
            s += __shfl_xor_sync(0xffffffffu, s, 1);
            s += __shfl_xor_sync(0xffffffffu, s, 2);
            float mu = s * (1.0f/96.0f);
            float ssq = 0.0f;
            #pragma unroll
            for (int i = 0; i < 24; i++){ float dv = g[i]-mu; ssq += dv*dv; }
            ssq += __shfl_xor_sync(0xffffffffu, ssq, 1);
            ssq += __shfl_xor_sync(0xffffffffu, ssq, 2);
            float r = rsqrtf(ssq * (1.0f/96.0f) + LN_EPS);

            float w  = ew[eid];
            float dr = ed[2*eid+1];
            float* ow = out_wm + (size_t)eid*FF;
            float* ap = g_agg + (size_t)dstI*FF;
            #pragma unroll
            for (int nt = 0; nt < 12; nt++){
                int c = nt*8 + c0;
                float y0 = ((g[2*nt]  -mu)*r*gmS[c]   + beS[c])   * w;
                float y1 = ((g[2*nt+1]-mu)*r*gmS[c+1] + beS[c+1]) * w;
                *(float2*)(ow + c) = make_float2(y0, y1);
                atomicAdd(ap + c,     y0*dr);
                atomicAdd(ap + c + 1, y1*dr);
            }
        }
    }
}

// ================= qkvg: warp-mma + prefetched A loads =================
#define QST 200
#define QRB (QST*2)
#define Q_BIAS 0
#define Q_WH   512
#define Q_WL   (Q_WH + 96*QRB)
#define QKVG_SMEM (Q_WL + 96*QRB)

__global__ __launch_bounds__(256,2)
void qkvg_mma_kernel(const float* __restrict__ nodes,
    const float* __restrict__ Wq, const float* __restrict__ bq,
    const float* __restrict__ Wk, const float* __restrict__ bk,
    const float* __restrict__ Wv, const float* __restrict__ bv,
    const float* __restrict__ Wg, const float* __restrict__ bg){
    extern __shared__ char smem[];
    uint32_t sb = smem_u32(smem);
    int tid = threadIdx.x, wid = tid >> 5, lane = tid & 31;
    int m = blockIdx.y;
    const float* WA = (m==0)?Wq:((m==1)?Wk:((m==2)?Wv:Wg));
    const float* bA = (m==0)?bq:((m==1)?bk:((m==2)?bv:bg));
    float* outA     = (m==0)?g_q:((m==1)?g_k:((m==2)?g_v:g_gate));
    bool isGate = (m == 3);

    float* biasS = (float*)(smem + Q_BIAS);

    for (int idx = tid; idx < K2*FF; idx += 256){
        int k = idx / FF, n = idx % FF;
        float w = WA[idx];
        __nv_bfloat16 hb = __float2bfloat16_rn(w);
        float hf = __bfloat162float(hb);
        __nv_bfloat16 lb = __float2bfloat16_rn(w - hf);
        *(__nv_bfloat16*)(smem + Q_WH + n*QRB + k*2) = hb;
        *(__nv_bfloat16*)(smem + Q_WL + n*QRB + k*2) = lb;
    }
    if (tid < FF) biasS[tid] = bA[tid];
    __syncthreads();

    uint32_t bRow = (uint32_t)((lane & 7) + ((lane >> 4) & 1)*8);
    uint32_t bOff = bRow*QRB + (((lane >> 3) & 1) * 16);
    uint32_t wh_base = sb + Q_WH + bOff;
    uint32_t wl_base = sb + Q_WL + bOff;

    int kk = 2*(lane & 3);

    int strip = blockIdx.x*8 + wid;
    int r0 = strip*16 + (lane >> 2);
    int r1 = r0 + 8;
    const float* n0p = nodes + (size_t)r0*FF;
    const float* n1p = nodes + (size_t)r1*FF;
    const float* a0p = g_agg + (size_t)r0*FF;
    const float* a1p = g_agg + (size_t)r1*FF;

    float d[12][4];
    #pragma unroll
    for (int nt = 0; nt < 12; nt++){ d[nt][0]=d[nt][1]=d[nt][2]=d[nt][3]=0.0f; }

    float2 f0 = *(const float2*)(n0p + kk);
    float2 f1 = *(const float2*)(n1p + kk);
    float2 f2 = *(const float2*)(n0p + kk + 8);
    float2 f3 = *(const float2*)(n1p + kk + 8);

    #pragma unroll 1
    for (int kt = 0; kt < 12; kt++){
        float2 nx0, nx1, nx2, nx3;
        if (kt < 11){
            int kn = kt + 1;
            const float *p0, *p1;
            if (kn < 6){ int ko = kn*16;      p0 = n0p + ko; p1 = n1p + ko; }
            else       { int ko = kn*16 - 96; p0 = a0p + ko; p1 = a1p + ko; }
            nx0 = *(const float2*)(p0 + kk);
            nx1 = *(const float2*)(p1 + kk);
            nx2 = *(const float2*)(p0 + kk + 8);
            nx3 = *(const float2*)(p1 + kk + 8);
        }

        uint32_t Ah[4], Al[4];
        bf16_split2(f0.x, f0.y, Ah[0], Al[0]);
        bf16_split2(f1.x, f1.y, Ah[1], Al[1]);
        bf16_split2(f2.x, f2.y, Ah[2], Al[2]);
        bf16_split2(f3.x, f3.y, Ah[3], Al[3]);

        #pragma unroll
        for (int g = 0; g < 6; g++){
            uint32_t Bh[4], Bl[4];
            ldsm4(Bh, wh_base + (uint32_t)(g*16*QRB) + kt*32);
            ldsm4(Bl, wl_base + (uint32_t)(g*16*QRB) + kt*32);
            mma16816(d[2*g],   Ah, Bh);     mma16816(d[2*g],   Al, Bh);     mma16816(d[2*g],   Ah, Bl);
            mma16816(d[2*g+1], Ah, Bh+2);   mma16816(d[2*g+1], Al, Bh+2);   mma16816(d[2*g+1], Ah, Bl+2);
        }
        f0 = nx0; f1 = nx1; f2 = nx2; f3 = nx3;
    }

    #pragma unroll
    for (int j = 0; j < 2; j++){
        int row = j ? r1 : r0;
        int b = row >> 10, n = row & (NN-1);
        #pragma unroll
        for (int nt = 0; nt < 12; nt++){
            float v0 = d[nt][2*j]   + biasS[nt*8 + kk];
            float v1 = d[nt][2*j+1] + biasS[nt*8 + kk + 1];
            if (isGate){
                v0 = 1.0f/(1.0f + __expf(-v0));
                v1 = 1.0f/(1.0f + __expf(-v1));
            }
            size_t off = ((size_t)(b*HH + nt)*NN + n)*DD + kk;
            *(float2*)(outA + off) = make_float2(v0, v1);
        }
    }
}

// ================= attention: warp-mma flash (R12 winner, unchanged) =================
#define A_OKH 0
#define A_OKL 16384
#define A_OVH 32768
#define A_OVL 49280
#define A_VSTRIDE 2064
#define ATTN_SMEM 66048
#define KSB 64

__global__ __launch_bounds__(256,2)
void attn_mma_kernel(){
    extern __shared__ char smem[];
    uint32_t sb = smem_u32(smem);
    int bh = blockIdx.x;
    int b = bh / HH, h = bh % HH;
    int tid = threadIdx.x, wid = tid >> 5, lane = tid & 31;

    for (int j = tid; j < NN; j += 256){
        const float4* kp = (const float4*)(g_k + ((size_t)bh*NN + j)*DD);
        float4 k0 = kp[0], k1 = kp[1];
        uint32_t h0,h1,h2,h3,l0,l1,l2,l3;
        bf16_split2(k0.x,k0.y,h0,l0); bf16_split2(k0.z,k0.w,h1,l1);
        bf16_split2(k1.x,k1.y,h2,l2); bf16_split2(k1.z,k1.w,h3,l3);
        *(uint4*)(smem + A_OKH + j*16) = make_uint4(h0,h1,h2,h3);
        *(uint4*)(smem + A_OKL + j*16) = make_uint4(l0,l1,l2,l3);

        const float4* vp = (const float4*)(g_v + ((size_t)bh*NN + j)*DD);
        float4 v0 = vp[0], v1 = vp[1];
        float vv[8] = {v0.x,v0.y,v0.z,v0.w,v1.x,v1.y,v1.z,v1.w};
        #pragma unroll
        for (int d = 0; d < 8; d++){
            __nv_bfloat16 hb = __float2bfloat16_rn(vv[d]);
            float hf = __bfloat162float(hb);
            __nv_bfloat16 lb = __float2bfloat16_rn(vv[d] - hf);
            *(__nv_bfloat16*)(smem + A_OVH + d*A_VSTRIDE + j*2) = hb;
            *(__nv_bfloat16*)(smem + A_OVL + d*A_VSTRIDE + j*2) = lb;
        }
    }
    __syncthreads();

    int r0 = blockIdx.y*128 + wid*16 + (lane >> 2);
    int r1 = r0 + 8;
    int c0 = 2*(lane & 3);
    float2 q0 = *(const float2*)(g_q + ((size_t)bh*NN + r0)*DD + c0);
    float2 q1 = *(const float2*)(g_q + ((size_t)bh*NN + r1)*DD + c0);
    uint32_t Ah[2], Al[2];
    bf16_split2(q0.x*ATT_SCALE, q0.y*ATT_SCALE, Ah[0], Al[0]);
    bf16_split2(q1.x*ATT_SCALE, q1.y*ATT_SCALE, Ah[1], Al[1]);

    float m0 = -3.4e38f, m1 = -3.4e38f, la0 = 0.0f, la1 = 0.0f;
    float O[4] = {0.0f, 0.0f, 0.0f, 0.0f};

    uint32_t vBase = (lane & 7)*A_VSTRIDE + ((lane >> 3) & 3)*16;

    #pragma unroll 1
    for (int kb = 0; kb < NN/KSB; kb++){
        uint32_t kh[8], kl[8];
        ldsm4(kh,     sb + A_OKH + (kb*KSB + lane)*16);
        ldsm4(kh + 4, sb + A_OKH + (kb*KSB + 32 + lane)*16);
        ldsm4(kl,     sb + A_OKL + (kb*KSB + lane)*16);
        ldsm4(kl + 4, sb + A_OKL + (kb*KSB + 32 + lane)*16);

        float s[8][4];
        #pragma unroll
        for (int nt = 0; nt < 8; nt++){ s[nt][0]=s[nt][1]=s[nt][2]=s[nt][3]=0.0f; }
        #pragma unroll
        for (int nt = 0; nt < 8; nt++){
            mma1688(s[nt], Ah, kh[nt]);
            mma1688(s[nt], Al, kh[nt]);
            mma1688(s[nt], Ah, kl[nt]);
        }

        float bm0 = s[0][0], bm1 = s[0][2];
        #pragma unroll
        for (int nt = 0; nt < 8; nt++){
            bm0 = fmaxf(bm0, fmaxf(s[nt][0], s[nt][1]));
            bm1 = fmaxf(bm1, fmaxf(s[nt][2], s[nt][3]));
        }
        bm0 = fmaxf(bm0, __shfl_xor_sync(0xffffffffu, bm0, 1));
        bm0 = fmaxf(bm0, __shfl_xor_sync(0xffffffffu, bm0, 2));
        bm1 = fmaxf(bm1, __shfl_xor_sync(0xffffffffu, bm1, 1));
        bm1 = fmaxf(bm1, __shfl_xor_sync(0xffffffffu, bm1, 2));
        float mn0 = fmaxf(m0, bm0), mn1 = fmaxf(m1, bm1);
        float fac0 = __expf(m0 - mn0), fac1 = __expf(m1 - mn1);
        m0 = mn0; m1 = mn1;
        O[0] *= fac0; O[1] *= fac0; O[2] *= fac1; O[3] *= fac1;

        uint32_t vh[8], vl[8];
        uint32_t vaddr = sb + vBase + kb*KSB*2;
        ldsm4(vh,     A_OVH + vaddr);
        ldsm4(vh + 4, A_OVH + vaddr + 64);
        ldsm4(vl,     A_OVL + vaddr);
        ldsm4(vl + 4, A_OVL + vaddr + 64);

        float rs0 = 0.0f, rs1 = 0.0f;
        #pragma unroll
        for (int kt = 0; kt < 4; kt++){
            float p0 = __expf(s[2*kt][0]   - mn0);
            float p1 = __expf(s[2*kt][1]   - mn0);
            float p2 = __expf(s[2*kt][2]   - mn1);
            float p3 = __expf(s[2*kt][3]   - mn1);
            float p4 = __expf(s[2*kt+1][0] - mn0);
            float p5 = __expf(s[2*kt+1][1] - mn0);
            float p6 = __expf(s[2*kt+1][2] - mn1);
            float p7 = __expf(s[2*kt+1][3] - mn1);
            rs0 += (p0 + p1) + (p4 + p5);
            rs1 += (p2 + p3) + (p6 + p7);
            uint32_t Ph[4], Pl[4];
            bf16_split2(p0, p1, Ph[0], Pl[0]);
            bf16_split2(p2, p3, Ph[1], Pl[1]);
            bf16_split2(p4, p5, Ph[2], Pl[2]);
            bf16_split2(p6, p7, Ph[3], Pl[3]);
            mma16816(O, Ph, vh + kt*2);
            mma16816(O, Pl, vh + kt*2);
            mma16816(O, Ph, vl + kt*2);
        }
        rs0 += __shfl_xor_sync(0xffffffffu, rs0, 1);
        rs0 += __shfl_xor_sync(0xffffffffu, rs0, 2);
        rs1 += __shfl_xor_sync(0xffffffffu, rs1, 1);
        rs1 += __shfl_xor_sync(0xffffffffu, rs1, 2);
        la0 = la0*fac0 + rs0;
        la1 = la1*fac1 + rs1;
    }

    float inv0 = 1.0f / la0, inv1 = 1.0f / la1;
    float2 g0 = *(const float2*)(g_gate + ((size_t)bh*NN + r0)*DD + c0);
    float2 g1 = *(const float2*)(g_gate + ((size_t)bh*NN + r1)*DD + c0);
    *(float2*)(g_att + ((size_t)((b<<10) + r0))*FF + h*DD + c0) =
        make_float2(O[0]*inv0*g0.x, O[1]*inv0*g0.y);
    *(float2*)(g_att + ((size_t)((b<<10) + r1))*FF + h*DD + c0) =
        make_float2(O[2]*inv1*g1.x, O[3]*inv1*g1.y);
}

// ================= output: warp-mma LN(GELU(att @ Wo + bo)) =================
#define OST 104
#define ORB (OST*2)          // 208 B row stride
#define O_BIAS 0
#define O_GU   384
#define O_BE   768
#define O_WH   1152
#define O_WL   (O_WH + 96*ORB)
#define OUT_SMEM (O_WL + 96*ORB)

__global__ __launch_bounds__(256,2)
void out_mma_kernel(const float* __restrict__ Wo, const float* __restrict__ bo,
                    const float* __restrict__ gu, const float* __restrict__ betau,
                    float* __restrict__ out){
    extern __shared__ char smem[];
    uint32_t sb = smem_u32(smem);
    int tid = threadIdx.x, wid = tid >> 5, lane = tid & 31;

    float* biasS = (float*)(smem + O_BIAS);
    float* guS   = (float*)(smem + O_GU);
    float* beS   = (float*)(smem + O_BE);

    for (int idx = tid; idx < FF*FF; idx += 256){
        int k = idx / FF, n = idx % FF;
        float w = Wo[idx];
        __nv_bfloat16 hb = __float2bfloat16_rn(w);
        float hf = __bfloat162float(hb);
        __nv_bfloat16 lb = __float2bfloat16_rn(w - hf);
        *(__nv_bfloat16*)(smem + O_WH + n*ORB + k*2) = hb;
        *(__nv_bfloat16*)(smem + O_WL + n*ORB + k*2) = lb;
    }
    if (tid < FF){ biasS[tid] = bo[tid]; guS[tid] = gu[tid]; beS[tid] = betau[tid]; }
    __syncthreads();

    uint32_t bRow = (uint32_t)((lane & 7) + ((lane >> 4) & 1)*8);
    uint32_t bOff = bRow*ORB + (((lane >> 3) & 1) * 16);
    uint32_t wh_base = sb + O_WH + bOff;
    uint32_t wl_base = sb + O_WL + bOff;

    int kk = 2*(lane & 3);
    int strip = blockIdx.x*8 + wid;           // 512 strips, grid 64 x 8 warps
    int r0 = strip*16 + (lane >> 2);
    int r1 = r0 + 8;
    const float* a0p = g_att + (size_t)r0*FF;
    const float* a1p = g_att + (size_t)r1*FF;

    float d[12][4];
    #pragma unroll
    for (int nt = 0; nt < 12; nt++){ d[nt][0]=d[nt][1]=d[nt][2]=d[nt][3]=0.0f; }

    float2 f0 = *(const float2*)(a0p + kk);
    float2 f1 = *(const float2*)(a1p + kk);
    float2 f2 = *(const float2*)(a0p + kk + 8);
    float2 f3 = *(const float2*)(a1p + kk + 8);

    #pragma unroll 1
    for (int kt = 0; kt < 6; kt++){
        float2 nx0, nx1, nx2, nx3;
        if (kt < 5){
            int ko = (kt+1)*16;
            nx0 = *(const float2*)(a0p + ko + kk);
            nx1 = *(const float2*)(a1p + ko + kk);
            nx2 = *(const float2*)(a0p + ko + kk + 8);
            nx3 = *(const float2*)(a1p + ko + kk + 8);
        }
        uint32_t Ah[4], Al[4];
        bf16_split2(f0.x, f0.y, Ah[0], Al[0]);
        bf16_split2(f1.x, f1.y, Ah[1], Al[1]);
        bf16_split2(f2.x, f2.y, Ah[2], Al[2]);
        bf16_split2(f3.x, f3.y, Ah[3], Al[3]);

        #pragma unroll
        for (int g = 0; g < 6; g++){
            uint32_t Bh[4], Bl[4];
            ldsm4(Bh, wh_base + (uint32_t)(g*16*ORB) + kt*32);
            ldsm4(Bl, wl_base + (uint32_t)(g*16*ORB) + kt*32);
            mma16816(d[2*g],   Ah, Bh);     mma16816(d[2*g],   Al, Bh);     mma16816(d[2*g],   Ah, Bl);
            mma16816(d[2*g+1], Ah, Bh+2);   mma16816(d[2*g+1], Al, Bh+2);   mma16816(d[2*g+1], Ah, Bl+2);
        }
        f0 = nx0; f1 = nx1; f2 = nx2; f3 = nx3;
    }

    #pragma unroll
    for (int j = 0; j < 2; j++){
        int row = j ? r1 : r0;
        int c0 = kk;

        float g[24];
        float s = 0.0f;
        #pragma unroll
        for (int nt = 0; nt < 12; nt++){
            int c = nt*8 + c0;
            float v0 = gelu_erf(d[nt][2*j]   + biasS[c]);
            float v1 = gelu_erf(d[nt][2*j+1] + biasS[c+1]);
            g[2*nt] = v0; g[2*nt+1] = v1;
            s += v0 + v1;
        }
        s += __shfl_xor_sync(0xffffffffu, s, 1);
        s += __shfl_xor_sync(0xffffffffu, s, 2);
        float mu = s * (1.0f/96.0f);
        float ssq = 0.0f;
        #pragma unroll
        for (int i = 0; i < 24; i++){ float dv = g[i]-mu; ssq += dv*dv; }
        ssq += __shfl_xor_sync(0xffffffffu, ssq, 1);
        ssq += __shfl_xor_sync(0xffffffffu, ssq, 2);
        float r = rsqrtf(ssq * (1.0f/96.0f) + LN_EPS);

        float* op = out + (size_t)row*FF;
        #pragma unroll
        for (int nt = 0; nt < 12; nt++){
            int c = nt*8 + c0;
            float y0 = (g[2*nt]  -mu)*r*guS[c]   + beS[c];
            float y1 = (g[2*nt+1]-mu)*r*guS[c+1] + beS[c+1];
            *(float2*)(op + c) = make_float2(y0, y1);
        }
    }
}

// ---------------- launch ----------------
extern "C" void kernel_launch(void* const* d_in, const int* in_sizes, int n_in,
                              void* d_out, int out_size){
    const float* nodes = (const float*)d_in[0];
    const float* efeat = (const float*)d_in[1];
    const int*   edges = (const int*)  d_in[2];
    const float* ew    = (const float*)d_in[3];
    const float* ed    = (const float*)d_in[4];
    const float* Wm    = (const float*)d_in[5];
    const float* bm    = (const float*)d_in[6];
    const float* gm    = (const float*)d_in[7];
    const float* betam = (const float*)d_in[8];
    const float* Wq=(const float*)d_in[9],  *bq=(const float*)d_in[10];
    const float* Wk=(const float*)d_in[11], *bk=(const float*)d_in[12];
    const float* Wv=(const float*)d_in[13], *bv=(const float*)d_in[14];
    const float* Wg=(const float*)d_in[15], *bg=(const float*)d_in[16];
    const float* Wo=(const float*)d_in[17], *bo=(const float*)d_in[18];
    const float* gu=(const float*)d_in[19], *betau=(const float*)d_in[20];
    float* out = (float*)d_out;

    const size_t OFF_WM    = (size_t)BB*NN*FF;
    const size_t OFF_EDGES = OFF_WM + (size_t)BB*EE*FF;
    const size_t OFF_EW    = OFF_EDGES + (size_t)BB*EE*2;
    const size_t OFF_ED    = OFF_EW + (size_t)BB*EE;

    cudaFuncSetAttribute(msg_mma_kernel,  cudaFuncAttributeMaxDynamicSharedMemorySize, MSG_SMEM);
    cudaFuncSetAttribute(qkvg_mma_kernel, cudaFuncAttributeMaxDynamicSharedMemorySize, QKVG_SMEM);
    cudaFuncSetAttribute(attn_mma_kernel, cudaFuncAttributeMaxDynamicSharedMemorySize, ATTN_SMEM);
    cudaFuncSetAttribute(out_mma_kernel,  cudaFuncAttributeMaxDynamicSharedMemorySize, OUT_SMEM);

    prep_kernel<<<(BB*NN*FF+255)/256, 256>>>(edges, ew, ed,
                                             out+OFF_EDGES, out+OFF_EW, out+OFF_ED);
    msg_mma_kernel<<<296, 256, MSG_SMEM>>>(nodes, efeat, edges, ew, ed,
                                           Wm, bm, gm, betam, out+OFF_WM);
    qkvg_mma_kernel<<<dim3(64,4), 256, QKVG_SMEM>>>(nodes, Wq,bq, Wk,bk, Wv,bv, Wg,bg);
    attn_mma_kernel<<<dim3(BB*HH,8), 256, ATTN_SMEM>>>();
    out_mma_kernel<<<64, 256, OUT_SMEM>>>(Wo, bo, gu, betau, out);
}

// round 17
// speedup vs baseline: 2.5190x; 1.0648x over previous
#include <cuda_runtime.h>
#include <cuda_bf16.h>
#include <math.h>
#include <stdint.h>

#define BB 8
#define NN 1024
#define EE 16384
#define FF 96
#define FE 32
#define HH 12
#define DD 8
#define KM 224
#define K2 192
#define LN_EPS 1e-3f
#define ATT_SCALE 0.35355339059327373f
#define ATT_SCALE_L2E 0.5101288491015279f   // ATT_SCALE * log2(e)

typedef unsigned long long u64;

__device__ __forceinline__ float gelu_erf(float x){
    return 0.5f * x * (1.0f + erff(x * 0.70710678118654752f));
}

// ---------------- warp-mma helpers ----------------
__device__ __forceinline__ uint32_t smem_u32(const void* p){
    uint32_t a;
    asm("{ .reg .u64 t; cvta.to.shared.u64 t, %1; cvt.u32.u64 %0, t; }" : "=r"(a) : "l"(p));
    return a;
}
__device__ __forceinline__ void ldsm4(uint32_t* r, uint32_t addr){
    asm volatile("ldmatrix.sync.aligned.m8n8.x4.shared.b16 {%0,%1,%2,%3}, [%4];"
        : "=r"(r[0]), "=r"(r[1]), "=r"(r[2]), "=r"(r[3]) : "r"(addr));
}
__device__ __forceinline__ void mma16816(float* d, const uint32_t* a, const uint32_t* b){
    asm volatile("mma.sync.aligned.m16n8k16.row.col.f32.bf16.bf16.f32 "
        "{%0,%1,%2,%3}, {%4,%5,%6,%7}, {%8,%9}, {%0,%1,%2,%3};"
        : "+f"(d[0]), "+f"(d[1]), "+f"(d[2]), "+f"(d[3])
        : "r"(a[0]), "r"(a[1]), "r"(a[2]), "r"(a[3]), "r"(b[0]), "r"(b[1]));
}
__device__ __forceinline__ void mma16816b(float* d, const uint32_t* a, uint32_t b0, uint32_t b1){
    asm volatile("mma.sync.aligned.m16n8k16.row.col.f32.bf16.bf16.f32 "
        "{%0,%1,%2,%3}, {%4,%5,%6,%7}, {%8,%9}, {%0,%1,%2,%3};"
        : "+f"(d[0]), "+f"(d[1]), "+f"(d[2]), "+f"(d[3])
        : "r"(a[0]), "r"(a[1]), "r"(a[2]), "r"(a[3]), "r"(b0), "r"(b1));
}
__device__ __forceinline__ void mma1688(float* d, const uint32_t* a, uint32_t b){
    asm volatile("mma.sync.aligned.m16n8k8.row.col.f32.bf16.bf16.f32 "
        "{%0,%1,%2,%3}, {%4,%5}, {%6}, {%0,%1,%2,%3};"
        : "+f"(d[0]), "+f"(d[1]), "+f"(d[2]), "+f"(d[3])
        : "r"(a[0]), "r"(a[1]), "r"(b));
}
__device__ __forceinline__ void bf16_split2(float x0, float x1, uint32_t &h, uint32_t &l){
    asm("cvt.rn.bf16x2.f32 %0, %1, %2;" : "=r"(h) : "f"(x1), "f"(x0));
    float h0 = __uint_as_float(h << 16);
    float h1 = __uint_as_float(h & 0xffff0000u);
    float r0 = x0 - h0, r1 = x1 - h1;
    asm("cvt.rn.bf16x2.f32 %0, %1, %2;" : "=r"(l) : "f"(r1), "f"(r0));
}
__device__ __forceinline__ float ex2f(float x){
    float y; asm("ex2.approx.f32 %0, %1;" : "=f"(y) : "f"(x)); return y;
}
__device__ __forceinline__ u64 pack2(float a, float b){
    u64 r; asm("mov.b64 %0, {%1, %2};" : "=l"(r) : "f"(a), "f"(b)); return r;
}
__device__ __forceinline__ float2 unpack2(u64 v){
    float2 f; asm("mov.b64 {%0, %1}, %2;" : "=f"(f.x), "=f"(f.y) : "l"(v)); return f;
}
__device__ __forceinline__ void red_add_v4(float* p, float a, float b, float c, float d){
    u64 g; asm("cvta.to.global.u64 %0, %1;" : "=l"(g) : "l"(p));
    asm volatile("red.global.add.v4.f32 [%0], {%1,%2,%3,%4};"
        :: "l"(g), "f"(a), "f"(b), "f"(c), "f"(d) : "memory");
}

// ---------------- scratch ----------------
__device__ float g_agg [BB*NN*FF];
__device__ float g_q   [BB*HH*NN*DD];
__device__ float g_k   [BB*HH*NN*DD];
__device__ float g_v   [BB*HH*NN*DD];
__device__ float g_gate[BB*HH*NN*DD];
__device__ float g_att [BB*NN*FF];

// ---------------- fused zero_agg + passthrough ----------------
__global__ void prep_kernel(const int* __restrict__ edges,
                            const float* __restrict__ ew,
                            const float* __restrict__ ed,
                            float* __restrict__ out_edges,
                            float* __restrict__ out_ew,
                            float* __restrict__ out_ed){
    int i = blockIdx.x*blockDim.x + threadIdx.x;
    if (i < BB*NN*FF) g_agg[i] = 0.0f;
    if (i < BB*EE*2){ out_edges[i] = (float)edges[i]; out_ed[i] = ed[i]; }
    if (i < BB*EE)  out_ew[i] = ew[i];
}

// ================= message kernel: warp-mma + prefetch + v4 atomics =================
#define XST 232
#define XRB (XST*2)
#define OFF_BIAS 1024
#define OFF_GM   1408
#define OFF_BE   1792
#define OFF_WH   2304
#define OFF_WL   (OFF_WH + 96*XRB)
#define MSG_SMEM (OFF_WL + 96*XRB)
#define NSTRIPS (BB*EE/16)

__global__ __launch_bounds__(256,2)
void msg_mma_kernel(const float* __restrict__ nodes, const float* __restrict__ efeat,
                    const int* __restrict__ edges, const float* __restrict__ ew,
                    const float* __restrict__ ed, const float* __restrict__ Wm,
                    const float* __restrict__ bm, const float* __restrict__ gm,
                    const float* __restrict__ betam, float* __restrict__ out_wm){
    extern __shared__ char smem[];
    uint32_t sb = smem_u32(smem);
    int tid = threadIdx.x, wid = tid >> 5, lane = tid & 31;

    float* biasS = (float*)(smem + OFF_BIAS);
    float* gmS   = (float*)(smem + OFF_GM);
    float* beS   = (float*)(smem + OFF_BE);

    for (int idx = tid; idx < KM*FF; idx += 256){
        int k = idx / FF, n = idx % FF;
        float w = Wm[idx];
        __nv_bfloat16 hb = __float2bfloat16_rn(w);
        float hf = __bfloat162float(hb);
        __nv_bfloat16 lb = __float2bfloat16_rn(w - hf);
        *(__nv_bfloat16*)(smem + OFF_WH + n*XRB + k*2) = hb;
        *(__nv_bfloat16*)(smem + OFF_WL + n*XRB + k*2) = lb;
    }
    if (tid < FF){ biasS[tid] = bm[tid]; gmS[tid] = gm[tid]; beS[tid] = betam[tid]; }
    __syncthreads();

    uint32_t bRow = (uint32_t)((lane & 7) + ((lane >> 4) & 1)*8);
    uint32_t bOff = bRow*XRB + (((lane >> 3) & 1) * 16);
    uint32_t wh_base = sb + OFF_WH + bOff;
    uint32_t wl_base = sb + OFF_WL + bOff;

    int kk = 2*(lane & 3);

    for (int strip = blockIdx.x*8 + wid; strip < NSTRIPS; strip += gridDim.x*8){
        int e0 = strip*16 + (lane >> 2);
        int e1 = e0 + 8;
        int2 ep0 = *(const int2*)(edges + 2*e0);
        int2 ep1 = *(const int2*)(edges + 2*e1);
        int b0 = e0 >> 14, b1 = e1 >> 14;
        const float* src0 = nodes + (size_t)((b0<<10) + ep0.x)*FF;
        const float* dst0 = nodes + (size_t)((b0<<10) + ep0.y)*FF;
        const float* src1 = nodes + (size_t)((b1<<10) + ep1.x)*FF;
        const float* dst1 = nodes + (size_t)((b1<<10) + ep1.y)*FF;
        const float* ef0  = efeat + (size_t)e0*FE;
        const float* ef1  = efeat + (size_t)e1*FE;

        float d[12][4];
        #pragma unroll
        for (int nt = 0; nt < 12; nt++){ d[nt][0]=d[nt][1]=d[nt][2]=d[nt][3]=0.0f; }

        float2 f0 = *(const float2*)(src0 + kk);
        float2 f1 = *(const float2*)(src1 + kk);
        float2 f2 = *(const float2*)(src0 + kk + 8);
        float2 f3 = *(const float2*)(src1 + kk + 8);

        #pragma unroll 1
        for (int kt = 0; kt < 14; kt++){
            float2 n0, n1, n2, n3;
            if (kt < 13){
                int kn = kt + 1;
                const float *p0, *p1;
                if (kn < 6)      { int ko = kn*16;        p0 = src0 + ko; p1 = src1 + ko; }
                else if (kn < 12){ int ko = kn*16 - 96;   p0 = dst0 + ko; p1 = dst1 + ko; }
                else             { int ko = kn*16 - 192;  p0 = ef0  + ko; p1 = ef1  + ko; }
                n0 = *(const float2*)(p0 + kk);
                n1 = *(const float2*)(p1 + kk);
                n2 = *(const float2*)(p0 + kk + 8);
                n3 = *(const float2*)(p1 + kk + 8);
            }

            uint32_t Ah[4], Al[4];
            bf16_split2(f0.x, f0.y, Ah[0], Al[0]);
            bf16_split2(f1.x, f1.y, Ah[1], Al[1]);
            bf16_split2(f2.x, f2.y, Ah[2], Al[2]);
            bf16_split2(f3.x, f3.y, Ah[3], Al[3]);

            #pragma unroll
            for (int g = 0; g < 6; g++){
                uint32_t Bh[4], Bl[4];
                ldsm4(Bh, wh_base + (uint32_t)(g*16*XRB) + kt*32);
                ldsm4(Bl, wl_base + (uint32_t)(g*16*XRB) + kt*32);
                mma16816(d[2*g],   Ah, Bh);     mma16816(d[2*g],   Al, Bh);     mma16816(d[2*g],   Ah, Bl);
                mma16816(d[2*g+1], Ah, Bh+2);   mma16816(d[2*g+1], Al, Bh+2);   mma16816(d[2*g+1], Ah, Bl+2);
            }
            f0 = n0; f1 = n1; f2 = n2; f3 = n3;
        }

        #pragma unroll
        for (int j = 0; j < 2; j++){
            int eid = j ? e1 : e0;
            int dstI = j ? ((b1<<10) + ep1.y) : ((b0<<10) + ep0.y);
            int c0 = kk;

            float g[24];
            float s = 0.0f;
            #pragma unroll
            for (int nt = 0; nt < 12; nt++){
                int c = nt*8 + c0;
                float v0 = gelu_erf(d[nt][2*j]   + biasS[c]);
                float v1 = gelu_erf(d[nt][2*j+1] + biasS[c+1]);
                g[2*nt] = v0; g[2*nt+1] = v1;
                s += v0 + v1;
            }
            s += __shfl_xor_sync(0xffffffffu, s, 1);
            s += __shfl_xor_sync(0xffffffffu, s, 2);
            float mu = s * (1.0f/96.0f);
            float ssq = 0.0f;
            #pragma unroll
            for (int i = 0; i < 24; i++){ float dv = g[i]-mu; ssq += dv*dv; }
            ssq += __shfl_xor_sync(0xffffffffu, ssq, 1);
            ssq += __shfl_xor_sync(0xffffffffu, ssq, 2);
            float r = rsqrtf(ssq * (1.0f/96.0f) + LN_EPS);

            float w  = ew[eid];
            float dr = ed[2*eid+1];
            float* ow = out_wm + (size_t)eid*FF;
            float* ap = g_agg + (size_t)dstI*FF;
            #pragma unroll
            for (int nt = 0; nt < 12; nt++){
                int c = nt*8 + c0;
                float y0 = ((g[2*nt]  -mu)*r*gmS[c]   + beS[c])   * w;
                float y1 = ((g[2*nt+1]-mu)*r*gmS[c+1] + beS[c+1]) * w;
                *(float2*)(ow + c) = make_float2(y0, y1);
                // pair-merge via shfl, even lane issues one float4 RED (4x fewer lane-ops)
                u64 mine = pack2(y0*dr, y1*dr);
                u64 part = __shfl_xor_sync(0xffffffffu, mine, 1);
                if (!(lane & 1)){
                    float2 lo = unpack2(mine), hi = unpack2(part);
                    int cb = nt*8 + ((lane & 2) << 1);
                    red_add_v4(ap + cb, lo.x, lo.y, hi.x, hi.y);
                }
            }
        }
    }
}

// ================= qkvg: warp-mma + prefetched A loads (R16, unchanged) =================
#define QST 200
#define QRB (QST*2)
#define Q_BIAS 0
#define Q_WH   512
#define Q_WL   (Q_WH + 96*QRB)
#define QKVG_SMEM (Q_WL + 96*QRB)

__global__ __launch_bounds__(256,2)
void qkvg_mma_kernel(const float* __restrict__ nodes,
    const float* __restrict__ Wq, const float* __restrict__ bq,
    const float* __restrict__ Wk, const float* __restrict__ bk,
    const float* __restrict__ Wv, const float* __restrict__ bv,
    const float* __restrict__ Wg, const float* __restrict__ bg){
    extern __shared__ char smem[];
    uint32_t sb = smem_u32(smem);
    int tid = threadIdx.x, wid = tid >> 5, lane = tid & 31;
    int m = blockIdx.y;
    const float* WA = (m==0)?Wq:((m==1)?Wk:((m==2)?Wv:Wg));
    const float* bA = (m==0)?bq:((m==1)?bk:((m==2)?bv:bg));
    float* outA     = (m==0)?g_q:((m==1)?g_k:((m==2)?g_v:g_gate));
    bool isGate = (m == 3);

    float* biasS = (float*)(smem + Q_BIAS);

    for (int idx = tid; idx < K2*FF; idx += 256){
        int k = idx / FF, n = idx % FF;
        float w = WA[idx];
        __nv_bfloat16 hb = __float2bfloat16_rn(w);
        float hf = __bfloat162float(hb);
        __nv_bfloat16 lb = __float2bfloat16_rn(w - hf);
        *(__nv_bfloat16*)(smem + Q_WH + n*QRB + k*2) = hb;
        *(__nv_bfloat16*)(smem + Q_WL + n*QRB + k*2) = lb;
    }
    if (tid < FF) biasS[tid] = bA[tid];
    __syncthreads();

    uint32_t bRow = (uint32_t)((lane & 7) + ((lane >> 4) & 1)*8);
    uint32_t bOff = bRow*QRB + (((lane >> 3) & 1) * 16);
    uint32_t wh_base = sb + Q_WH + bOff;
    uint32_t wl_base = sb + Q_WL + bOff;

    int kk = 2*(lane & 3);

    int strip = blockIdx.x*8 + wid;
    int r0 = strip*16 + (lane >> 2);
    int r1 = r0 + 8;
    const float* n0p = nodes + (size_t)r0*FF;
    const float* n1p = nodes + (size_t)r1*FF;
    const float* a0p = g_agg + (size_t)r0*FF;
    const float* a1p = g_agg + (size_t)r1*FF;

    float d[12][4];
    #pragma unroll
    for (int nt = 0; nt < 12; nt++){ d[nt][0]=d[nt][1]=d[nt][2]=d[nt][3]=0.0f; }

    float2 f0 = *(const float2*)(n0p + kk);
    float2 f1 = *(const float2*)(n1p + kk);
    float2 f2 = *(const float2*)(n0p + kk + 8);
    float2 f3 = *(const float2*)(n1p + kk + 8);

    #pragma unroll 1
    for (int kt = 0; kt < 12; kt++){
        float2 nx0, nx1, nx2, nx3;
        if (kt < 11){
            int kn = kt + 1;
            const float *p0, *p1;
            if (kn < 6){ int ko = kn*16;      p0 = n0p + ko; p1 = n1p + ko; }
            else       { int ko = kn*16 - 96; p0 = a0p + ko; p1 = a1p + ko; }
            nx0 = *(const float2*)(p0 + kk);
            nx1 = *(const float2*)(p1 + kk);
            nx2 = *(const float2*)(p0 + kk + 8);
            nx3 = *(const float2*)(p1 + kk + 8);
        }

        uint32_t Ah[4], Al[4];
        bf16_split2(f0.x, f0.y, Ah[0], Al[0]);
        bf16_split2(f1.x, f1.y, Ah[1], Al[1]);
        bf16_split2(f2.x, f2.y, Ah[2], Al[2]);
        bf16_split2(f3.x, f3.y, Ah[3], Al[3]);

        #pragma unroll
        for (int g = 0; g < 6; g++){
            uint32_t Bh[4], Bl[4];
            ldsm4(Bh, wh_base + (uint32_t)(g*16*QRB) + kt*32);
            ldsm4(Bl, wl_base + (uint32_t)(g*16*QRB) + kt*32);
            mma16816(d[2*g],   Ah, Bh);     mma16816(d[2*g],   Al, Bh);     mma16816(d[2*g],   Ah, Bl);
            mma16816(d[2*g+1], Ah, Bh+2);   mma16816(d[2*g+1], Al, Bh+2);   mma16816(d[2*g+1], Ah, Bl+2);
        }
        f0 = nx0; f1 = nx1; f2 = nx2; f3 = nx3;
    }

    #pragma unroll
    for (int j = 0; j < 2; j++){
        int row = j ? r1 : r0;
        int b = row >> 10, n = row & (NN-1);
        #pragma unroll
        for (int nt = 0; nt < 12; nt++){
            float v0 = d[nt][2*j]   + biasS[nt*8 + kk];
            float v1 = d[nt][2*j+1] + biasS[nt*8 + kk + 1];
            if (isGate){
                v0 = 1.0f/(1.0f + __expf(-v0));
                v1 = 1.0f/(1.0f + __expf(-v1));
            }
            size_t off = ((size_t)(b*HH + nt)*NN + n)*DD + kk;
            *(float2*)(outA + off) = make_float2(v0, v1);
        }
    }
}

// ================= attention: warp-mma flash, packed QK + ex2 =================
#define A_OKH 0
#define A_OKL 16384
#define A_OVH 32768
#define A_OVL 49280
#define A_VSTRIDE 2064
#define ATTN_SMEM 66048
#define KSB 64

__global__ __launch_bounds__(256,2)
void attn_mma_kernel(){
    extern __shared__ char smem[];
    uint32_t sb = smem_u32(smem);
    int bh = blockIdx.x;
    int b = bh / HH, h = bh % HH;
    int tid = threadIdx.x, wid = tid >> 5, lane = tid & 31;

    for (int j = tid; j < NN; j += 256){
        const float4* kp = (const float4*)(g_k + ((size_t)bh*NN + j)*DD);
        float4 k0 = kp[0], k1 = kp[1];
        uint32_t h0,h1,h2,h3,l0,l1,l2,l3;
        bf16_split2(k0.x,k0.y,h0,l0); bf16_split2(k0.z,k0.w,h1,l1);
        bf16_split2(k1.x,k1.y,h2,l2); bf16_split2(k1.z,k1.w,h3,l3);
        *(uint4*)(smem + A_OKH + j*16) = make_uint4(h0,h1,h2,h3);
        *(uint4*)(smem + A_OKL + j*16) = make_uint4(l0,l1,l2,l3);

        const float4* vp = (const float4*)(g_v + ((size_t)bh*NN + j)*DD);
        float4 v0 = vp[0], v1 = vp[1];
        float vv[8] = {v0.x,v0.y,v0.z,v0.w,v1.x,v1.y,v1.z,v1.w};
        #pragma unroll
        for (int d = 0; d < 8; d++){
            __nv_bfloat16 hb = __float2bfloat16_rn(vv[d]);
            float hf = __bfloat162float(hb);
            __nv_bfloat16 lb = __float2bfloat16_rn(vv[d] - hf);
            *(__nv_bfloat16*)(smem + A_OVH + d*A_VSTRIDE + j*2) = hb;
            *(__nv_bfloat16*)(smem + A_OVL + d*A_VSTRIDE + j*2) = lb;
        }
    }
    __syncthreads();

    // Q fragments pre-scaled by ATT_SCALE*log2(e); scores come out in log2 units
    int r0 = blockIdx.y*128 + wid*16 + (lane >> 2);
    int r1 = r0 + 8;
    int c0 = 2*(lane & 3);
    float2 q0 = *(const float2*)(g_q + ((size_t)bh*NN + r0)*DD + c0);
    float2 q1 = *(const float2*)(g_q + ((size_t)bh*NN + r1)*DD + c0);
    uint32_t Ah[2], Al[2];
    bf16_split2(q0.x*ATT_SCALE_L2E, q0.y*ATT_SCALE_L2E, Ah[0], Al[0]);
    bf16_split2(q1.x*ATT_SCALE_L2E, q1.y*ATT_SCALE_L2E, Ah[1], Al[1]);
    uint32_t A16[4] = {Ah[0], Ah[1], Al[0], Al[1]};   // k0-7 = Qh, k8-15 = Ql

    float m0 = -3.4e38f, m1 = -3.4e38f, la0 = 0.0f, la1 = 0.0f;
    float O[4] = {0.0f, 0.0f, 0.0f, 0.0f};

    uint32_t vBase = (lane & 7)*A_VSTRIDE + ((lane >> 3) & 3)*16;

    #pragma unroll 1
    for (int kb = 0; kb < NN/KSB; kb++){
        uint32_t kh[8], kl[8];
        ldsm4(kh,     sb + A_OKH + (kb*KSB + lane)*16);
        ldsm4(kh + 4, sb + A_OKH + (kb*KSB + 32 + lane)*16);
        ldsm4(kl,     sb + A_OKL + (kb*KSB + lane)*16);
        ldsm4(kl + 4, sb + A_OKL + (kb*KSB + 32 + lane)*16);

        float s[8][4];
        #pragma unroll
        for (int nt = 0; nt < 8; nt++){ s[nt][0]=s[nt][1]=s[nt][2]=s[nt][3]=0.0f; }
        #pragma unroll
        for (int nt = 0; nt < 8; nt++){
            mma16816b(s[nt], A16, kh[nt], kh[nt]);   // (Qh+Ql)·Kh in one mma
            mma1688(s[nt], Ah, kl[nt]);              // + Qh·Kl
        }

        float bm0 = s[0][0], bm1 = s[0][2];
        #pragma unroll
        for (int nt = 0; nt < 8; nt++){
            bm0 = fmaxf(bm0, fmaxf(s[nt][0], s[nt][1]));
            bm1 = fmaxf(bm1, fmaxf(s[nt][2], s[nt][3]));
        }
        bm0 = fmaxf(bm0, __shfl_xor_sync(0xffffffffu, bm0, 1));
        bm0 = fmaxf(bm0, __shfl_xor_sync(0xffffffffu, bm0, 2));
        bm1 = fmaxf(bm1, __shfl_xor_sync(0xffffffffu, bm1, 1));
        bm1 = fmaxf(bm1, __shfl_xor_sync(0xffffffffu, bm1, 2));
        float mn0 = fmaxf(m0, bm0), mn1 = fmaxf(m1, bm1);
        float fac0 = ex2f(m0 - mn0), fac1 = ex2f(m1 - mn1);
        m0 = mn0; m1 = mn1;
        O[0] *= fac0; O[1] *= fac0; O[2] *= fac1; O[3] *= fac1;

        uint32_t vh[8], vl[8];
        uint32_t vaddr = sb + vBase + kb*KSB*2;
        ldsm4(vh,     A_OVH + vaddr);
        ldsm4(vh + 4, A_OVH + vaddr + 64);
        ldsm4(vl,     A_OVL + vaddr);
        ldsm4(vl + 4, A_OVL + vaddr + 64);

        float rs0 = 0.0f, rs1 = 0.0f;
        #pragma unroll
        for (int kt = 0; kt < 4; kt++){
            float p0 = ex2f(s[2*kt][0]   - mn0);
            float p1 = ex2f(s[2*kt][1]   - mn0);
            float p2 = ex2f(s[2*kt][2]   - mn1);
            float p3 = ex2f(s[2*kt][3]   - mn1);
            float p4 = ex2f(s[2*kt+1][0] - mn0);
            float p5 = ex2f(s[2*kt+1][1] - mn0);
            float p6 = ex2f(s[2*kt+1][2] - mn1);
            float p7 = ex2f(s[2*kt+1][3] - mn1);
            rs0 += (p0 + p1) + (p4 + p5);
            rs1 += (p2 + p3) + (p6 + p7);
            uint32_t Ph[4], Pl[4];
            bf16_split2(p0, p1, Ph[0], Pl[0]);
            bf16_split2(p2, p3, Ph[1], Pl[1]);
            bf16_split2(p4, p5, Ph[2], Pl[2]);
            bf16_split2(p6, p7, Ph[3], Pl[3]);
            mma16816(O, Ph, vh + kt*2);
            mma16816(O, Pl, vh + kt*2);
            mma16816(O, Ph, vl + kt*2);
        }
        rs0 += __shfl_xor_sync(0xffffffffu, rs0, 1);
        rs0 += __shfl_xor_sync(0xffffffffu, rs0, 2);
        rs1 += __shfl_xor_sync(0xffffffffu, rs1, 1);
        rs1 += __shfl_xor_sync(0xffffffffu, rs1, 2);
        la0 = la0*fac0 + rs0;
        la1 = la1*fac1 + rs1;
    }

    float inv0 = 1.0f / la0, inv1 = 1.0f / la1;
    float2 g0 = *(const float2*)(g_gate + ((size_t)bh*NN + r0)*DD + c0);
    float2 g1 = *(const float2*)(g_gate + ((size_t)bh*NN + r1)*DD + c0);
    *(float2*)(g_att + ((size_t)((b<<10) + r0))*FF + h*DD + c0) =
        make_float2(O[0]*inv0*g0.x, O[1]*inv0*g0.y);
    *(float2*)(g_att + ((size_t)((b<<10) + r1))*FF + h*DD + c0) =
        make_float2(O[2]*inv1*g1.x, O[3]*inv1*g1.y);
}

// ================= output: warp-mma LN(GELU(att @ Wo + bo)) (R16, unchanged) =================
#define OST 104
#define ORB (OST*2)
#define O_BIAS 0
#define O_GU   384
#define O_BE   768
#define O_WH   1152
#define O_WL   (O_WH + 96*ORB)
#define OUT_SMEM (O_WL + 96*ORB)

__global__ __launch_bounds__(256,2)
void out_mma_kernel(const float* __restrict__ Wo, const float* __restrict__ bo,
                    const float* __restrict__ gu, const float* __restrict__ betau,
                    float* __restrict__ out){
    extern __shared__ char smem[];
    uint32_t sb = smem_u32(smem);
    int tid = threadIdx.x, wid = tid >> 5, lane = tid & 31;

    float* biasS = (float*)(smem + O_BIAS);
    float* guS   = (float*)(smem + O_GU);
    float* beS   = (float*)(smem + O_BE);

    for (int idx = tid; idx < FF*FF; idx += 256){
        int k = idx / FF, n = idx % FF;
        float w = Wo[idx];
        __nv_bfloat16 hb = __float2bfloat16_rn(w);
        float hf = __bfloat162float(hb);
        __nv_bfloat16 lb = __float2bfloat16_rn(w - hf);
        *(__nv_bfloat16*)(smem + O_WH + n*ORB + k*2) = hb;
        *(__nv_bfloat16*)(smem + O_WL + n*ORB + k*2) = lb;
    }
    if (tid < FF){ biasS[tid] = bo[tid]; guS[tid] = gu[tid]; beS[tid] = betau[tid]; }
    __syncthreads();

    uint32_t bRow = (uint32_t)((lane & 7) + ((lane >> 4) & 1)*8);
    uint32_t bOff = bRow*ORB + (((lane >> 3) & 1) * 16);
    uint32_t wh_base = sb + O_WH + bOff;
    uint32_t wl_base = sb + O_WL + bOff;

    int kk = 2*(lane & 3);
    int strip = blockIdx.x*8 + wid;
    int r0 = strip*16 + (lane >> 2);
    int r1 = r0 + 8;
    const float* a0p = g_att + (size_t)r0*FF;
    const float* a1p = g_att + (size_t)r1*FF;

    float d[12][4];
    #pragma unroll
    for (int nt = 0; nt < 12; nt++){ d[nt][0]=d[nt][1]=d[nt][2]=d[nt][3]=0.0f; }

    float2 f0 = *(const float2*)(a0p + kk);
    float2 f1 = *(const float2*)(a1p + kk);
    float2 f2 = *(const float2*)(a0p + kk + 8);
    float2 f3 = *(const float2*)(a1p + kk + 8);

    #pragma unroll 1
    for (int kt = 0; kt < 6; kt++){
        float2 nx0, nx1, nx2, nx3;
        if (kt < 5){
            int ko = (kt+1)*16;
            nx0 = *(const float2*)(a0p + ko + kk);
            nx1 = *(const float2*)(a1p + ko + kk);
            nx2 = *(const float2*)(a0p + ko + kk + 8);
            nx3 = *(const float2*)(a1p + ko + kk + 8);
        }
        uint32_t Ah[4], Al[4];
        bf16_split2(f0.x, f0.y, Ah[0], Al[0]);
        bf16_split2(f1.x, f1.y, Ah[1], Al[1]);
        bf16_split2(f2.x, f2.y, Ah[2], Al[2]);
        bf16_split2(f3.x, f3.y, Ah[3], Al[3]);

        #pragma unroll
        for (int g = 0; g < 6; g++){
            uint32_t Bh[4], Bl[4];
            ldsm4(Bh, wh_base + (uint32_t)(g*16*ORB) + kt*32);
            ldsm4(Bl, wl_base + (uint32_t)(g*16*ORB) + kt*32);
            mma16816(d[2*g],   Ah, Bh);     mma16816(d[2*g],   Al, Bh);     mma16816(d[2*g],   Ah, Bl);
            mma16816(d[2*g+1], Ah, Bh+2);   mma16816(d[2*g+1], Al, Bh+2);   mma16816(d[2*g+1], Ah, Bl+2);
        }
        f0 = nx0; f1 = nx1; f2 = nx2; f3 = nx3;
    }

    #pragma unroll
    for (int j = 0; j < 2; j++){
        int row = j ? r1 : r0;
        int c0 = kk;

        float g[24];
        float s = 0.0f;
        #pragma unroll
        for (int nt = 0; nt < 12; nt++){
            int c = nt*8 + c0;
            float v0 = gelu_erf(d[nt][2*j]   + biasS[c]);
            float v1 = gelu_erf(d[nt][2*j+1] + biasS[c+1]);
            g[2*nt] = v0; g[2*nt+1] = v1;
            s += v0 + v1;
        }
        s += __shfl_xor_sync(0xffffffffu, s, 1);
        s += __shfl_xor_sync(0xffffffffu, s, 2);
        float mu = s * (1.0f/96.0f);
        float ssq = 0.0f;
        #pragma unroll
        for (int i = 0; i < 24; i++){ float dv = g[i]-mu; ssq += dv*dv; }
        ssq += __shfl_xor_sync(0xffffffffu, ssq, 1);
        ssq += __shfl_xor_sync(0xffffffffu, ssq, 2);
        float r = rsqrtf(ssq * (1.0f/96.0f) + LN_EPS);

        float* op = out + (size_t)row*FF;
        #pragma unroll
        for (int nt = 0; nt < 12; nt++){
            int c = nt*8 + c0;
            float y0 = (g[2*nt]  -mu)*r*guS[c]   + beS[c];
            float y1 = (g[2*nt+1]-mu)*r*guS[c+1] + beS[c+1];
            *(float2*)(op + c) = make_float2(y0, y1);
        }
    }
}

// ---------------- launch ----------------
extern "C" void kernel_launch(void* const* d_in, const int* in_sizes, int n_in,
                              void* d_out, int out_size){
    const float* nodes = (const float*)d_in[0];
    const float* efeat = (const float*)d_in[1];
    const int*   edges = (const int*)  d_in[2];
    const float* ew    = (const float*)d_in[3];
    const float* ed    = (const float*)d_in[4];
    const float* Wm    = (const float*)d_in[5];
    const float* bm    = (const float*)d_in[6];
    const float* gm    = (const float*)d_in[7];
    const float* betam = (const float*)d_in[8];
    const float* Wq=(const float*)d_in[9],  *bq=(const float*)d_in[10];
    const float* Wk=(const float*)d_in[11], *bk=(const float*)d_in[12];
    const float* Wv=(const float*)d_in[13], *bv=(const float*)d_in[14];
    const float* Wg=(const float*)d_in[15], *bg=(const float*)d_in[16];
    const float* Wo=(const float*)d_in[17], *bo=(const float*)d_in[18];
    const float* gu=(const float*)d_in[19], *betau=(const float*)d_in[20];
    float* out = (float*)d_out;

    const size_t OFF_WM    = (size_t)BB*NN*FF;
    const size_t OFF_EDGES = OFF_WM + (size_t)BB*EE*FF;
    const size_t OFF_EW    = OFF_EDGES + (size_t)BB*EE*2;
    const size_t OFF_ED    = OFF_EW + (size_t)BB*EE;

    cudaFuncSetAttribute(msg_mma_kernel,  cudaFuncAttributeMaxDynamicSharedMemorySize, MSG_SMEM);
    cudaFuncSetAttribute(qkvg_mma_kernel, cudaFuncAttributeMaxDynamicSharedMemorySize, QKVG_SMEM);
    cudaFuncSetAttribute(attn_mma_kernel, cudaFuncAttributeMaxDynamicSharedMemorySize, ATTN_SMEM);
    cudaFuncSetAttribute(out_mma_kernel,  cudaFuncAttributeMaxDynamicSharedMemorySize, OUT_SMEM);

    prep_kernel<<<(BB*NN*FF+255)/256, 256>>>(edges, ew, ed,
                                             out+OFF_EDGES, out+OFF_EW, out+OFF_ED);
    msg_mma_kernel<<<296, 256, MSG_SMEM>>>(nodes, efeat, edges, ew, ed,
                                           Wm, bm, gm, betam, out+OFF_WM);
    qkvg_mma_kernel<<<dim3(64,4), 256, QKVG_SMEM>>>(nodes, Wq,bq, Wk,bk, Wv,bv, Wg,bg);
    attn_mma_kernel<<<dim3(BB*HH,8), 256, ATTN_SMEM>>>();
    out_mma_kernel<<<64, 256, OUT_SMEM>>>(Wo, bo, gu, betau, out);
}